// round 13
// baseline (speedup 1.0000x reference)
#include <cuda_runtime.h>
#include <cuda_fp16.h>
#include <math.h>
#include <stdint.h>

#define NN 50000
#define EE 800000

// ---------------- scratch (static __device__, allocation-free) ----------------
__device__ __half d_x16[NN * 256];
__device__ __half d_hA[2][NN * 192];
__device__ __half d_hB[2][NN * 192];
__device__ __half d_g16[2][NN * 128];
__device__ __half d_t16[2][NN * 64];
__device__ __half d_w16all[6][192 * 256];
__device__ int   d_cnt[2][NN];
__device__ int   d_rp[2][NN + 1];
__device__ int   d_cur[2][NN];
__device__ int2  d_edge[2][EE];
__device__ int2  d_sd[EE];
__device__ float d_dinv[2][NN];
__device__ int   d_bsum[2][512];
__device__ int   d_boff[2][512];
__device__ int   d_flag[1];

__device__ __forceinline__ uint32_t smem_u32(const void* p) {
    uint32_t a;
    asm("{ .reg .u64 t; cvta.to.shared.u64 t, %1; cvt.u32.u64 %0, t; }" : "=r"(a) : "l"(p));
    return a;
}
__device__ __forceinline__ float tanh_fast(float x) {
    float y;
    asm("tanh.approx.f32 %0, %1;" : "=f"(y) : "f"(x));
    return y;
}
__device__ __forceinline__ void cp_async16(uint32_t dst, const void* src, uint32_t src_bytes) {
    asm volatile("cp.async.cg.shared.global [%0], [%1], 16, %2;"
                 :: "r"(dst), "l"(src), "r"(src_bytes) : "memory");
}
#define CP_COMMIT() asm volatile("cp.async.commit_group;" ::: "memory")
#define CP_WAIT(N)  asm volatile("cp.async.wait_group %0;" :: "n"(N) : "memory")

// ---------------- graph build ----------------
__global__ void zero_detect_kernel(const int* ei32, int n) {
    int i = blockIdx.x * blockDim.x + threadIdx.x;
    if (i < n) { d_cnt[0][i] = 0; d_cnt[1][i] = 0; }
    if (blockIdx.x == 0) {
        __shared__ int any;
        if (threadIdx.x == 0) any = 0;
        __syncthreads();
        if (ei32[2 * threadIdx.x + 1] != 0) atomicExch(&any, 1);
        __syncthreads();
        if (threadIdx.x == 0) d_flag[0] = (any == 0) ? 1 : 0;
    }
}

__device__ __forceinline__ void load_edge(const void* ei, int e, int t, int& s, int& d) {
    if (d_flag[0]) {
        const long long* p = (const long long*)ei;
        s = (int)p[t]; d = (int)p[e + t];
    } else {
        const int* p = (const int*)ei;
        s = p[t]; d = p[e + t];
    }
}

__global__ void hist_kernel(const void* ei, int e) {
    int t = blockIdx.x * blockDim.x + threadIdx.x;
    if (t >= e) return;
    int s, d;
    load_edge(ei, e, t, s, d);
    d_sd[t] = make_int2(s, d);
    atomicAdd(&d_cnt[0][d], 1);
    atomicAdd(&d_cnt[1][s], 1);
}

__global__ void scan1_kernel(int n) {
    int g = blockIdx.y;
    int i = blockIdx.x * 512 + threadIdx.x;
    __shared__ int sh[512];
    sh[threadIdx.x] = (i < n) ? d_cnt[g][i] : 0;
    __syncthreads();
    for (int off = 256; off > 0; off >>= 1) {
        if (threadIdx.x < off) sh[threadIdx.x] += sh[threadIdx.x + off];
        __syncthreads();
    }
    if (threadIdx.x == 0) d_bsum[g][blockIdx.x] = sh[0];
}

__global__ void scan2_kernel(int nchunks, int n) {
    int t = threadIdx.x;
    int g = t >> 9, i = t & 511;
    __shared__ int sh[1024];
    int v = (i < nchunks) ? d_bsum[g][i] : 0;
    int orig = v;
    sh[t] = v;
    __syncthreads();
    for (int off = 1; off < 512; off <<= 1) {
        int add = (i >= off) ? sh[t - off] : 0;
        __syncthreads();
        sh[t] += add;
        __syncthreads();
    }
    d_boff[g][i] = sh[t] - orig;
    if (i == 511) d_rp[g][n] = sh[t];
}

__global__ void scan3_kernel(int n) {
    int g = blockIdx.y;
    int t = threadIdx.x;
    int i = blockIdx.x * 512 + t;
    __shared__ int sh[512];
    int c = (i < n) ? d_cnt[g][i] : 0;
    sh[t] = c;
    __syncthreads();
    for (int off = 1; off < 512; off <<= 1) {
        int add = (t >= off) ? sh[t - off] : 0;
        __syncthreads();
        sh[t] += add;
        __syncthreads();
    }
    if (i < n) {
        int excl = sh[t] - c + d_boff[g][blockIdx.x];
        d_rp[g][i] = excl;
        d_cur[g][i] = excl;
        d_dinv[g][i] = rsqrtf((float)c + 1.0f);
    }
}

__global__ void place_kernel(int e) {
    int t = blockIdx.x * blockDim.x + threadIdx.x;
    if (t >= e) return;
    int2 sd = d_sd[t];
    int s = sd.x, d = sd.y;
    float w0 = d_dinv[0][s] * d_dinv[0][d];
    int p0 = atomicAdd(&d_cur[0][d], 1);
    d_edge[0][p0] = make_int2(s, __float_as_int(w0));
    float w1 = d_dinv[1][s] * d_dinv[1][d];
    int p1 = atomicAdd(&d_cur[1][s], 1);
    d_edge[1][p1] = make_int2(d, __float_as_int(w1));
}

// ---------------- conversions ----------------
__global__ void convx_kernel(const float* __restrict__ x, int n4) {
    int i = blockIdx.x * blockDim.x + threadIdx.x;
    if (i >= n4) return;
    float4 v = reinterpret_cast<const float4*>(x)[i];
    reinterpret_cast<__half2*>(d_x16)[i * 2] = __floats2half2_rn(v.x, v.y);
    reinterpret_cast<__half2*>(d_x16)[i * 2 + 1] = __floats2half2_rn(v.z, v.w);
}

struct WPtrs { const float* w[6]; };

__global__ void convw_all_kernel(WPtrs wp) {
    int s = blockIdx.y;
    int din = ((s % 3) == 0) ? 256 : 192;
    int idx = blockIdx.x * 256 + threadIdx.x;
    if (idx >= 192 * din) return;
    int r = idx / din, k = idx - r * din;
    d_w16all[s][r * 256 + k] = __float2half(wp.w[s][((r >> 6) * din + k) * 64 + (r & 63)]);
}

// ---------------- mma.sync GEMM, double-buffered cp.async ----------------
#define KC 64
#define SKA 72
#define A_CH (128 * SKA)
#define B_CH (192 * SKA)
#define BUF_CH (A_CH + B_CH)

__global__ void __launch_bounds__(256) gemm_mma_kernel(
    const __half* __restrict__ H0, const __half* __restrict__ H1,
    int wslot, int din, int n,
    const float* __restrict__ bias0, const float* __restrict__ bias1,
    float* __restrict__ z, __half* __restrict__ h0, __half* __restrict__ h1)
{
    int enc = blockIdx.y;
    const __half* __restrict__ H = enc ? H1 : H0;
    const float* __restrict__ bias = enc ? bias1 : bias0;
    float* zout = z ? z + (size_t)enc * n * 192 : nullptr;
    __half* h16out = enc ? h1 : h0;
    const __half* __restrict__ Wm = d_w16all[enc * 3 + wslot];
    __half* __restrict__ g16 = d_g16[enc];

    extern __shared__ __half smh[];
    int tid = threadIdx.x, wid = tid >> 5, lane = tid & 31;
    int row0 = blockIdx.x * 128;
    int nk = din / KC;

    uint32_t sbase = smem_u32(smh);

    auto load_chunk = [&](int b, int kc) {
        uint32_t abuf = sbase + (uint32_t)(b * BUF_CH) * 2u;
        uint32_t bbuf = abuf + (uint32_t)A_CH * 2u;
        int k0 = kc * KC;
#pragma unroll
        for (int i = 0; i < 4; i++) {
            int idx = tid + 256 * i;
            int r = idx >> 3, c16 = idx & 7;
            const __half* src = H + (size_t)(row0 + r) * din + k0 + c16 * 8;
            uint32_t ok = (row0 + r < n) ? 16u : 0u;
            cp_async16(abuf + (uint32_t)(r * SKA + c16 * 8) * 2u, src, ok);
        }
#pragma unroll
        for (int i = 0; i < 6; i++) {
            int idx = tid + 256 * i;
            int r = idx >> 3, c16 = idx & 7;
            const __half* src = Wm + (size_t)r * 256 + k0 + c16 * 8;
            cp_async16(bbuf + (uint32_t)(r * SKA + c16 * 8) * 2u, src, 16u);
        }
        CP_COMMIT();
    };

    float acc[24][4];
#pragma unroll
    for (int i = 0; i < 24; i++)
#pragma unroll
        for (int j = 0; j < 4; j++) acc[i][j] = 0.f;

    int mrow = wid * 16;
    uint32_t a_off = (uint32_t)((mrow + (lane & 15)) * SKA + (lane >> 4) * 8) * 2u;
    uint32_t b_off = (uint32_t)((((lane >> 4) * 8 + (lane & 7)) * SKA) + ((lane >> 3) & 1) * 8) * 2u;
    uint32_t b_step2 = (uint32_t)(16 * SKA) * 2u;

    load_chunk(0, 0);

    for (int c = 0; c < nk; c++) {
        if (c + 1 < nk) {
            load_chunk((c + 1) & 1, c + 1);
            CP_WAIT(1);
        } else {
            CP_WAIT(0);
        }
        __syncthreads();
        uint32_t abuf = sbase + (uint32_t)((c & 1) * BUF_CH) * 2u;
        uint32_t bbuf = abuf + (uint32_t)A_CH * 2u;
#pragma unroll
        for (int ks = 0; ks < 4; ks++) {
            uint32_t a0, a1, a2, a3;
            asm volatile("ldmatrix.sync.aligned.m8n8.x4.shared.b16 {%0,%1,%2,%3}, [%4];"
                : "=r"(a0), "=r"(a1), "=r"(a2), "=r"(a3) : "r"(abuf + a_off + ks * 32));
            uint32_t bb = bbuf + b_off + ks * 32;
#pragma unroll
            for (int nt2 = 0; nt2 < 12; nt2++) {
                uint32_t b0r, b1r, b2r, b3r;
                asm volatile("ldmatrix.sync.aligned.m8n8.x4.shared.b16 {%0,%1,%2,%3}, [%4];"
                    : "=r"(b0r), "=r"(b1r), "=r"(b2r), "=r"(b3r) : "r"(bb));
                asm volatile("mma.sync.aligned.m16n8k16.row.col.f32.f16.f16.f32 "
                    "{%0,%1,%2,%3}, {%4,%5,%6,%7}, {%8,%9}, {%0,%1,%2,%3};"
                    : "+f"(acc[2*nt2][0]), "+f"(acc[2*nt2][1]), "+f"(acc[2*nt2][2]), "+f"(acc[2*nt2][3])
                    : "r"(a0), "r"(a1), "r"(a2), "r"(a3), "r"(b0r), "r"(b1r));
                asm volatile("mma.sync.aligned.m16n8k16.row.col.f32.f16.f16.f32 "
                    "{%0,%1,%2,%3}, {%4,%5,%6,%7}, {%8,%9}, {%0,%1,%2,%3};"
                    : "+f"(acc[2*nt2+1][0]), "+f"(acc[2*nt2+1][1]), "+f"(acc[2*nt2+1][2]), "+f"(acc[2*nt2+1][3])
                    : "r"(a0), "r"(a1), "r"(a2), "r"(a3), "r"(b2r), "r"(b3r));
                bb += b_step2;
            }
        }
        __syncthreads();
    }

    int r0 = row0 + mrow + (lane >> 2);
    int r1 = r0 + 8;
#pragma unroll
    for (int nt = 0; nt < 24; nt++) {
        int c = nt * 8 + (lane & 3) * 2;
        if (c < 64) {
            float vb0 = bias[c], vb1 = bias[c + 1];
            if (zout) {
                float o00 = tanhf(acc[nt][0] + vb0), o01 = tanhf(acc[nt][1] + vb1);
                float o10 = tanhf(acc[nt][2] + vb0), o11 = tanhf(acc[nt][3] + vb1);
                if (r0 < n) *reinterpret_cast<float2*>(zout + (size_t)r0 * 192 + c) = make_float2(o00, o01);
                if (r1 < n) *reinterpret_cast<float2*>(zout + (size_t)r1 * 192 + c) = make_float2(o10, o11);
            } else {
                float o00 = tanh_fast(acc[nt][0] + vb0), o01 = tanh_fast(acc[nt][1] + vb1);
                float o10 = tanh_fast(acc[nt][2] + vb0), o11 = tanh_fast(acc[nt][3] + vb1);
                if (r0 < n) *reinterpret_cast<__half2*>(h16out + (size_t)r0 * 192 + c) = __floats2half2_rn(o00, o01);
                if (r1 < n) *reinterpret_cast<__half2*>(h16out + (size_t)r1 * 192 + c) = __floats2half2_rn(o10, o11);
            }
        } else {
            int cg = c - 64;
            if (r0 < n) *reinterpret_cast<__half2*>(g16 + (size_t)r0 * 128 + cg) = __floats2half2_rn(acc[nt][0], acc[nt][1]);
            if (r1 < n) *reinterpret_cast<__half2*>(g16 + (size_t)r1 * 128 + cg) = __floats2half2_rn(acc[nt][2], acc[nt][3]);
        }
    }
}

// ------ fused prop over 128 cols: warp per row, broadcast edge loads (8-deep)
__global__ void prop_fused_kernel(int n,
                                  float* __restrict__ z, __half* __restrict__ h0, __half* __restrict__ h1,
                                  const float* __restrict__ b1_0, const float* __restrict__ b1_1)
{
    int enc = blockIdx.y;
    int row = blockIdx.x * 8 + (threadIdx.x >> 5);
    int lane = threadIdx.x & 31;
    if (row >= n) return;
    const __half* __restrict__ g16 = d_g16[enc];
    __half* __restrict__ t16 = d_t16[enc];
    float* zout = z ? z + (size_t)enc * n * 192 : nullptr;
    __half* h16out = enc ? h1 : h0;
    const float* __restrict__ b1 = enc ? b1_1 : b1_0;
    const int* __restrict__ rp = d_rp[enc];
    const int2* __restrict__ edg = d_edge[enc];

    float di = d_dinv[enc][row];
    float sw = di * di;
    uint2 su = reinterpret_cast<const uint2*>(g16 + (size_t)row * 128)[lane];
    float2 s0 = __half22float2(*reinterpret_cast<__half2*>(&su.x));
    float2 s1 = __half22float2(*reinterpret_cast<__half2*>(&su.y));
    float4 acc = make_float4(sw * s0.x, sw * s0.y, sw * s1.x, sw * s1.y);
    int beg = rp[row], end = rp[row + 1];

    float2 a0, a1;
#define ACC128(vv, wv_) \
    a0 = __half22float2(*reinterpret_cast<__half2*>(&vv.x)); \
    a1 = __half22float2(*reinterpret_cast<__half2*>(&vv.y)); \
    acc.x = fmaf(wv_, a0.x, acc.x); acc.y = fmaf(wv_, a0.y, acc.y); \
    acc.z = fmaf(wv_, a1.x, acc.z); acc.w = fmaf(wv_, a1.y, acc.w);

    int u = beg;
    for (; u + 8 <= end; u += 8) {
        int2 E0 = edg[u + 0]; int2 E1 = edg[u + 1];
        int2 E2 = edg[u + 2]; int2 E3 = edg[u + 3];
        int2 E4 = edg[u + 4]; int2 E5 = edg[u + 5];
        int2 E6 = edg[u + 6]; int2 E7 = edg[u + 7];
        uint2 v0 = reinterpret_cast<const uint2*>(g16 + (size_t)E0.x * 128)[lane];
        uint2 v1 = reinterpret_cast<const uint2*>(g16 + (size_t)E1.x * 128)[lane];
        uint2 v2 = reinterpret_cast<const uint2*>(g16 + (size_t)E2.x * 128)[lane];
        uint2 v3 = reinterpret_cast<const uint2*>(g16 + (size_t)E3.x * 128)[lane];
        uint2 v4 = reinterpret_cast<const uint2*>(g16 + (size_t)E4.x * 128)[lane];
        uint2 v5 = reinterpret_cast<const uint2*>(g16 + (size_t)E5.x * 128)[lane];
        uint2 v6 = reinterpret_cast<const uint2*>(g16 + (size_t)E6.x * 128)[lane];
        uint2 v7 = reinterpret_cast<const uint2*>(g16 + (size_t)E7.x * 128)[lane];
        ACC128(v0, __int_as_float(E0.y)) ACC128(v1, __int_as_float(E1.y))
        ACC128(v2, __int_as_float(E2.y)) ACC128(v3, __int_as_float(E3.y))
        ACC128(v4, __int_as_float(E4.y)) ACC128(v5, __int_as_float(E5.y))
        ACC128(v6, __int_as_float(E6.y)) ACC128(v7, __int_as_float(E7.y))
    }
    for (; u < end; u++) {
        int2 E = edg[u];
        uint2 vu = reinterpret_cast<const uint2*>(g16 + (size_t)E.x * 128)[lane];
        ACC128(vu, __int_as_float(E.y))
    }
#undef ACC128

    if (lane < 16) {
        int c = lane * 4;
        float4 o;
        if (zout) {
            o.x = tanhf(acc.x + b1[c + 0]); o.y = tanhf(acc.y + b1[c + 1]);
            o.z = tanhf(acc.z + b1[c + 2]); o.w = tanhf(acc.w + b1[c + 3]);
            reinterpret_cast<float4*>(zout + (size_t)row * 192 + 64)[lane] = o;
        } else {
            o.x = tanh_fast(acc.x + b1[c + 0]); o.y = tanh_fast(acc.y + b1[c + 1]);
            o.z = tanh_fast(acc.z + b1[c + 2]); o.w = tanh_fast(acc.w + b1[c + 3]);
            uint2 hu;
            __half2 q0 = __floats2half2_rn(o.x, o.y);
            __half2 q1 = __floats2half2_rn(o.z, o.w);
            hu.x = *reinterpret_cast<uint32_t*>(&q0);
            hu.y = *reinterpret_cast<uint32_t*>(&q1);
            reinterpret_cast<uint2*>(h16out + (size_t)row * 192 + 64)[lane] = hu;
        }
    } else {
        uint2 tu;
        __half2 q0 = __floats2half2_rn(acc.x, acc.y);
        __half2 q1 = __floats2half2_rn(acc.z, acc.w);
        tu.x = *reinterpret_cast<uint32_t*>(&q0);
        tu.y = *reinterpret_cast<uint32_t*>(&q1);
        reinterpret_cast<uint2*>(t16 + (size_t)row * 64)[lane - 16] = tu;
    }
}

// ------ second hop: warp per row, broadcast edge loads (16-deep) -------------
__global__ void prop64_kernel(int n,
                              float* __restrict__ z, __half* __restrict__ h0, __half* __restrict__ h1,
                              const float* __restrict__ b2_0, const float* __restrict__ b2_1)
{
    int enc = blockIdx.y;
    int row = blockIdx.x * 8 + (threadIdx.x >> 5);
    int lane = threadIdx.x & 31;
    if (row >= n) return;
    const __half* __restrict__ t16 = d_t16[enc];
    float* zout = z ? z + (size_t)enc * n * 192 : nullptr;
    __half* h16out = enc ? h1 : h0;
    const float* __restrict__ b2 = enc ? b2_1 : b2_0;
    const int* __restrict__ rp = d_rp[enc];
    const int2* __restrict__ edg = d_edge[enc];

    float di = d_dinv[enc][row];
    float sw = di * di;
    __half2 sh = reinterpret_cast<const __half2*>(t16 + (size_t)row * 64)[lane];
    float2 s = __half22float2(sh);
    float2 acc = make_float2(sw * s.x, sw * s.y);
    int beg = rp[row], end = rp[row + 1];

    float2 a;
#define ACC64(vv, wv_) \
    a = __half22float2(vv); \
    acc.x = fmaf(wv_, a.x, acc.x); acc.y = fmaf(wv_, a.y, acc.y);

    int u = beg;
    for (; u + 16 <= end; u += 16) {
        int2 E[16];
        __half2 V[16];
#pragma unroll
        for (int k = 0; k < 16; k++) E[k] = edg[u + k];
#pragma unroll
        for (int k = 0; k < 16; k++)
            V[k] = reinterpret_cast<const __half2*>(t16 + (size_t)E[k].x * 64)[lane];
#pragma unroll
        for (int k = 0; k < 16; k++) {
            ACC64(V[k], __int_as_float(E[k].y))
        }
    }
    for (; u + 8 <= end; u += 8) {
        int2 E[8];
        __half2 V[8];
#pragma unroll
        for (int k = 0; k < 8; k++) E[k] = edg[u + k];
#pragma unroll
        for (int k = 0; k < 8; k++)
            V[k] = reinterpret_cast<const __half2*>(t16 + (size_t)E[k].x * 64)[lane];
#pragma unroll
        for (int k = 0; k < 8; k++) {
            ACC64(V[k], __int_as_float(E[k].y))
        }
    }
    for (; u < end; u++) {
        int2 E = edg[u];
        __half2 vh = reinterpret_cast<const __half2*>(t16 + (size_t)E.x * 64)[lane];
        ACC64(vh, __int_as_float(E.y))
    }
#undef ACC64

    int c = lane * 2;
    float2 o;
    if (zout) {
        o.x = tanhf(acc.x + b2[c + 0]);
        o.y = tanhf(acc.y + b2[c + 1]);
        reinterpret_cast<float2*>(zout + (size_t)row * 192 + 128)[lane] = o;
    } else {
        o.x = tanh_fast(acc.x + b2[c + 0]);
        o.y = tanh_fast(acc.y + b2[c + 1]);
        reinterpret_cast<__half2*>(h16out + (size_t)row * 192 + 128)[lane] = __floats2half2_rn(o.x, o.y);
    }
}

extern "C" void kernel_launch(void* const* d_in, const int* in_sizes, int n_in,
                              void* d_out, int out_size)
{
    const float* x = (const float*)d_in[0];
    const void* ei = d_in[1];
    int n = in_sizes[0] / 256;
    int e = in_sizes[1] / 2;
    if (n > NN) n = NN;
    if (e > EE) e = EE;

    static cudaStream_t s2 = nullptr;
    static cudaEvent_t evFork = nullptr, evJoin = nullptr;
    if (s2 == nullptr) {
        cudaStreamCreateWithFlags(&s2, cudaStreamNonBlocking);
        cudaEventCreateWithFlags(&evFork, cudaEventDisableTiming);
        cudaEventCreateWithFlags(&evJoin, cudaEventDisableTiming);
    }

    __half* x16 = nullptr; __half* hA0; __half* hA1; __half* hB0; __half* hB1;
    cudaGetSymbolAddress((void**)&x16, d_x16);
    cudaGetSymbolAddress((void**)&hA0, d_hA);
    hA1 = hA0 + (size_t)NN * 192;
    cudaGetSymbolAddress((void**)&hB0, d_hB);
    hB1 = hB0 + (size_t)NN * 192;

    const float* b1_0 = (const float*)d_in[3];
    const float* b2_0 = (const float*)d_in[5];
    const float* b3_0 = (const float*)d_in[7];
    const float* b1_1 = (const float*)d_in[9];
    const float* b2_1 = (const float*)d_in[11];
    const float* b3_1 = (const float*)d_in[13];
    float* z = (float*)d_out;

    int smem_gemm = 2 * BUF_CH * 2;
    cudaFuncSetAttribute(gemm_mma_kernel, cudaFuncAttributeMaxDynamicSharedMemorySize, smem_gemm);

    dim3 ggrid((n + 127) / 128, 2);
    dim3 pgrid((n + 7) / 8, 2);

    WPtrs wp;
    for (int i = 0; i < 6; i++) wp.w[i] = (const float*)d_in[2 + (i / 3) * 6 + (i % 3) * 2];

    // ---- fork: side stream does conversions + layer-1 GEMM (graph-independent)
    cudaEventRecord(evFork, 0);
    cudaStreamWaitEvent(s2, evFork, 0);
    convx_kernel<<<(n * 64 + 255) / 256, 256, 0, s2>>>(x, n * 64);
    convw_all_kernel<<<dim3((192 * 256 + 255) / 256, 6), 256, 0, s2>>>(wp);
    gemm_mma_kernel<<<ggrid, 256, smem_gemm, s2>>>(x16, x16, 0, 256, n, b1_0, b1_1, nullptr, hA0, hA1);
    cudaEventRecord(evJoin, s2);

    // ---- main stream: graph build chain
    zero_detect_kernel<<<(n + 255) / 256, 256>>>((const int*)ei, n);
    hist_kernel<<<(e + 255) / 256, 256>>>(ei, e);
    int nchunks = (n + 511) / 512;
    dim3 sgrid(nchunks, 2);
    scan1_kernel<<<sgrid, 512>>>(n);
    scan2_kernel<<<1, 1024>>>(nchunks, n);
    scan3_kernel<<<sgrid, 512>>>(n);
    place_kernel<<<(e + 255) / 256, 256>>>(e);

    // ---- join
    cudaStreamWaitEvent(0, evJoin, 0);

    prop_fused_kernel<<<pgrid, 256>>>(n, nullptr, hA0, hA1, b1_0 + 64, b1_1 + 64);
    prop64_kernel<<<pgrid, 256>>>(n, nullptr, hA0, hA1, b1_0 + 128, b1_1 + 128);
    // layer 2
    gemm_mma_kernel<<<ggrid, 256, smem_gemm>>>(hA0, hA1, 1, 192, n, b2_0, b2_1, nullptr, hB0, hB1);
    prop_fused_kernel<<<pgrid, 256>>>(n, nullptr, hB0, hB1, b2_0 + 64, b2_1 + 64);
    prop64_kernel<<<pgrid, 256>>>(n, nullptr, hB0, hB1, b2_0 + 128, b2_1 + 128);
    // layer 3 -> z (fp32 output)
    gemm_mma_kernel<<<ggrid, 256, smem_gemm>>>(hB0, hB1, 2, 192, n, b3_0, b3_1, z, nullptr, nullptr);
    prop_fused_kernel<<<pgrid, 256>>>(n, z, nullptr, nullptr, b3_0 + 64, b3_1 + 64);
    prop64_kernel<<<pgrid, 256>>>(n, z, nullptr, nullptr, b3_0 + 128, b3_1 + 128);
}

// round 14
// speedup vs baseline: 1.0152x; 1.0152x over previous
#include <cuda_runtime.h>
#include <cuda_fp16.h>
#include <math.h>
#include <stdint.h>

#define NN 50000
#define EE 800000

// ---------------- scratch (static __device__, allocation-free) ----------------
__device__ __half d_x16[NN * 256];
__device__ __half d_hA[2][NN * 192];
__device__ __half d_hB[2][NN * 192];
__device__ __half d_g16[2][NN * 128];
__device__ __half d_t16[2][NN * 64];
__device__ __half d_w16all[6][192 * 256];
__device__ int   d_cnt[2][NN];
__device__ int   d_rp[2][NN + 1];
__device__ int   d_cur[2][NN];
__device__ int2  d_edge[2][EE];
__device__ int2  d_sd[EE];
__device__ float d_dinv[2][NN];
__device__ int   d_bsum[2][512];
__device__ int   d_boff[2][512];
__device__ int   d_flag[1];

__device__ __forceinline__ uint32_t smem_u32(const void* p) {
    uint32_t a;
    asm("{ .reg .u64 t; cvta.to.shared.u64 t, %1; cvt.u32.u64 %0, t; }" : "=r"(a) : "l"(p));
    return a;
}
__device__ __forceinline__ float tanh_fast(float x) {
    float y;
    asm("tanh.approx.f32 %0, %1;" : "=f"(y) : "f"(x));
    return y;
}
__device__ __forceinline__ void cp_async16(uint32_t dst, const void* src, uint32_t src_bytes) {
    asm volatile("cp.async.cg.shared.global [%0], [%1], 16, %2;"
                 :: "r"(dst), "l"(src), "r"(src_bytes) : "memory");
}
#define CP_COMMIT() asm volatile("cp.async.commit_group;" ::: "memory")
#define CP_WAIT(N)  asm volatile("cp.async.wait_group %0;" :: "n"(N) : "memory")

// ---------------- graph build ----------------
__global__ void zero_detect_kernel(const int* ei32, int n) {
    int i = blockIdx.x * blockDim.x + threadIdx.x;
    if (i < n) { d_cnt[0][i] = 0; d_cnt[1][i] = 0; }
    if (blockIdx.x == 0) {
        __shared__ int any;
        if (threadIdx.x == 0) any = 0;
        __syncthreads();
        if (ei32[2 * threadIdx.x + 1] != 0) atomicExch(&any, 1);
        __syncthreads();
        if (threadIdx.x == 0) d_flag[0] = (any == 0) ? 1 : 0;
    }
}

__device__ __forceinline__ void load_edge(const void* ei, int e, int t, int& s, int& d) {
    if (d_flag[0]) {
        const long long* p = (const long long*)ei;
        s = (int)p[t]; d = (int)p[e + t];
    } else {
        const int* p = (const int*)ei;
        s = p[t]; d = p[e + t];
    }
}

__global__ void hist_kernel(const void* ei, int e) {
    int t = blockIdx.x * blockDim.x + threadIdx.x;
    if (t >= e) return;
    int s, d;
    load_edge(ei, e, t, s, d);
    d_sd[t] = make_int2(s, d);
    atomicAdd(&d_cnt[0][d], 1);
    atomicAdd(&d_cnt[1][s], 1);
}

__global__ void scan1_kernel(int n) {
    int g = blockIdx.y;
    int i = blockIdx.x * 512 + threadIdx.x;
    __shared__ int sh[512];
    sh[threadIdx.x] = (i < n) ? d_cnt[g][i] : 0;
    __syncthreads();
    for (int off = 256; off > 0; off >>= 1) {
        if (threadIdx.x < off) sh[threadIdx.x] += sh[threadIdx.x + off];
        __syncthreads();
    }
    if (threadIdx.x == 0) d_bsum[g][blockIdx.x] = sh[0];
}

__global__ void scan2_kernel(int nchunks, int n) {
    int t = threadIdx.x;
    int g = t >> 9, i = t & 511;
    __shared__ int sh[1024];
    int v = (i < nchunks) ? d_bsum[g][i] : 0;
    int orig = v;
    sh[t] = v;
    __syncthreads();
    for (int off = 1; off < 512; off <<= 1) {
        int add = (i >= off) ? sh[t - off] : 0;
        __syncthreads();
        sh[t] += add;
        __syncthreads();
    }
    d_boff[g][i] = sh[t] - orig;
    if (i == 511) d_rp[g][n] = sh[t];
}

__global__ void scan3_kernel(int n) {
    int g = blockIdx.y;
    int t = threadIdx.x;
    int i = blockIdx.x * 512 + t;
    __shared__ int sh[512];
    int c = (i < n) ? d_cnt[g][i] : 0;
    sh[t] = c;
    __syncthreads();
    for (int off = 1; off < 512; off <<= 1) {
        int add = (t >= off) ? sh[t - off] : 0;
        __syncthreads();
        sh[t] += add;
        __syncthreads();
    }
    if (i < n) {
        int excl = sh[t] - c + d_boff[g][blockIdx.x];
        d_rp[g][i] = excl;
        d_cur[g][i] = excl;
        d_dinv[g][i] = rsqrtf((float)c + 1.0f);
    }
}

__global__ void place_kernel(int e) {
    int t = blockIdx.x * blockDim.x + threadIdx.x;
    if (t >= e) return;
    int2 sd = d_sd[t];
    int s = sd.x, d = sd.y;
    float w0 = d_dinv[0][s] * d_dinv[0][d];
    int p0 = atomicAdd(&d_cur[0][d], 1);
    d_edge[0][p0] = make_int2(s, __float_as_int(w0));
    float w1 = d_dinv[1][s] * d_dinv[1][d];
    int p1 = atomicAdd(&d_cur[1][s], 1);
    d_edge[1][p1] = make_int2(d, __float_as_int(w1));
}

// ---------------- conversions ----------------
__global__ void convx_kernel(const float* __restrict__ x, int n4) {
    int i = blockIdx.x * blockDim.x + threadIdx.x;
    if (i >= n4) return;
    float4 v = reinterpret_cast<const float4*>(x)[i];
    reinterpret_cast<__half2*>(d_x16)[i * 2] = __floats2half2_rn(v.x, v.y);
    reinterpret_cast<__half2*>(d_x16)[i * 2 + 1] = __floats2half2_rn(v.z, v.w);
}

struct WPtrs { const float* w[6]; };

__global__ void convw_all_kernel(WPtrs wp) {
    int s = blockIdx.y;
    int din = ((s % 3) == 0) ? 256 : 192;
    int idx = blockIdx.x * 256 + threadIdx.x;
    if (idx >= 192 * din) return;
    int r = idx / din, k = idx - r * din;
    d_w16all[s][r * 256 + k] = __float2half(wp.w[s][((r >> 6) * din + k) * 64 + (r & 63)]);
}

// ---------------- mma.sync GEMM, double-buffered cp.async ----------------
#define KC 64
#define SKA 72
#define A_CH (128 * SKA)
#define B_CH (192 * SKA)
#define BUF_CH (A_CH + B_CH)

__global__ void __launch_bounds__(256) gemm_mma_kernel(
    const __half* __restrict__ H0, const __half* __restrict__ H1,
    int wslot, int din, int n,
    const float* __restrict__ bias0, const float* __restrict__ bias1,
    float* __restrict__ z, __half* __restrict__ h0, __half* __restrict__ h1)
{
    int enc = blockIdx.y;
    const __half* __restrict__ H = enc ? H1 : H0;
    const float* __restrict__ bias = enc ? bias1 : bias0;
    float* zout = z ? z + (size_t)enc * n * 192 : nullptr;
    __half* h16out = enc ? h1 : h0;
    const __half* __restrict__ Wm = d_w16all[enc * 3 + wslot];
    __half* __restrict__ g16 = d_g16[enc];

    extern __shared__ __half smh[];
    int tid = threadIdx.x, wid = tid >> 5, lane = tid & 31;
    int row0 = blockIdx.x * 128;
    int nk = din / KC;

    uint32_t sbase = smem_u32(smh);

    auto load_chunk = [&](int b, int kc) {
        uint32_t abuf = sbase + (uint32_t)(b * BUF_CH) * 2u;
        uint32_t bbuf = abuf + (uint32_t)A_CH * 2u;
        int k0 = kc * KC;
#pragma unroll
        for (int i = 0; i < 4; i++) {
            int idx = tid + 256 * i;
            int r = idx >> 3, c16 = idx & 7;
            const __half* src = H + (size_t)(row0 + r) * din + k0 + c16 * 8;
            uint32_t ok = (row0 + r < n) ? 16u : 0u;
            cp_async16(abuf + (uint32_t)(r * SKA + c16 * 8) * 2u, src, ok);
        }
#pragma unroll
        for (int i = 0; i < 6; i++) {
            int idx = tid + 256 * i;
            int r = idx >> 3, c16 = idx & 7;
            const __half* src = Wm + (size_t)r * 256 + k0 + c16 * 8;
            cp_async16(bbuf + (uint32_t)(r * SKA + c16 * 8) * 2u, src, 16u);
        }
        CP_COMMIT();
    };

    float acc[24][4];
#pragma unroll
    for (int i = 0; i < 24; i++)
#pragma unroll
        for (int j = 0; j < 4; j++) acc[i][j] = 0.f;

    int mrow = wid * 16;
    uint32_t a_off = (uint32_t)((mrow + (lane & 15)) * SKA + (lane >> 4) * 8) * 2u;
    uint32_t b_off = (uint32_t)((((lane >> 4) * 8 + (lane & 7)) * SKA) + ((lane >> 3) & 1) * 8) * 2u;
    uint32_t b_step2 = (uint32_t)(16 * SKA) * 2u;

    load_chunk(0, 0);

    for (int c = 0; c < nk; c++) {
        if (c + 1 < nk) {
            load_chunk((c + 1) & 1, c + 1);
            CP_WAIT(1);
        } else {
            CP_WAIT(0);
        }
        __syncthreads();
        uint32_t abuf = sbase + (uint32_t)((c & 1) * BUF_CH) * 2u;
        uint32_t bbuf = abuf + (uint32_t)A_CH * 2u;
#pragma unroll
        for (int ks = 0; ks < 4; ks++) {
            uint32_t a0, a1, a2, a3;
            asm volatile("ldmatrix.sync.aligned.m8n8.x4.shared.b16 {%0,%1,%2,%3}, [%4];"
                : "=r"(a0), "=r"(a1), "=r"(a2), "=r"(a3) : "r"(abuf + a_off + ks * 32));
            uint32_t bb = bbuf + b_off + ks * 32;
#pragma unroll
            for (int nt2 = 0; nt2 < 12; nt2++) {
                uint32_t b0r, b1r, b2r, b3r;
                asm volatile("ldmatrix.sync.aligned.m8n8.x4.shared.b16 {%0,%1,%2,%3}, [%4];"
                    : "=r"(b0r), "=r"(b1r), "=r"(b2r), "=r"(b3r) : "r"(bb));
                asm volatile("mma.sync.aligned.m16n8k16.row.col.f32.f16.f16.f32 "
                    "{%0,%1,%2,%3}, {%4,%5,%6,%7}, {%8,%9}, {%0,%1,%2,%3};"
                    : "+f"(acc[2*nt2][0]), "+f"(acc[2*nt2][1]), "+f"(acc[2*nt2][2]), "+f"(acc[2*nt2][3])
                    : "r"(a0), "r"(a1), "r"(a2), "r"(a3), "r"(b0r), "r"(b1r));
                asm volatile("mma.sync.aligned.m16n8k16.row.col.f32.f16.f16.f32 "
                    "{%0,%1,%2,%3}, {%4,%5,%6,%7}, {%8,%9}, {%0,%1,%2,%3};"
                    : "+f"(acc[2*nt2+1][0]), "+f"(acc[2*nt2+1][1]), "+f"(acc[2*nt2+1][2]), "+f"(acc[2*nt2+1][3])
                    : "r"(a0), "r"(a1), "r"(a2), "r"(a3), "r"(b2r), "r"(b3r));
                bb += b_step2;
            }
        }
        __syncthreads();
    }

    int r0 = row0 + mrow + (lane >> 2);
    int r1 = r0 + 8;
#pragma unroll
    for (int nt = 0; nt < 24; nt++) {
        int c = nt * 8 + (lane & 3) * 2;
        if (c < 64) {
            float vb0 = bias[c], vb1 = bias[c + 1];
            float o00 = tanh_fast(acc[nt][0] + vb0), o01 = tanh_fast(acc[nt][1] + vb1);
            float o10 = tanh_fast(acc[nt][2] + vb0), o11 = tanh_fast(acc[nt][3] + vb1);
            if (zout) {
                if (r0 < n) *reinterpret_cast<float2*>(zout + (size_t)r0 * 192 + c) = make_float2(o00, o01);
                if (r1 < n) *reinterpret_cast<float2*>(zout + (size_t)r1 * 192 + c) = make_float2(o10, o11);
            } else {
                if (r0 < n) *reinterpret_cast<__half2*>(h16out + (size_t)r0 * 192 + c) = __floats2half2_rn(o00, o01);
                if (r1 < n) *reinterpret_cast<__half2*>(h16out + (size_t)r1 * 192 + c) = __floats2half2_rn(o10, o11);
            }
        } else {
            int cg = c - 64;
            if (r0 < n) *reinterpret_cast<__half2*>(g16 + (size_t)r0 * 128 + cg) = __floats2half2_rn(acc[nt][0], acc[nt][1]);
            if (r1 < n) *reinterpret_cast<__half2*>(g16 + (size_t)r1 * 128 + cg) = __floats2half2_rn(acc[nt][2], acc[nt][3]);
        }
    }
}

// ------ fused prop over 128 cols: warp per row, broadcast edge loads (8-deep)
__global__ void prop_fused_kernel(int n,
                                  float* __restrict__ z, __half* __restrict__ h0, __half* __restrict__ h1,
                                  const float* __restrict__ b1_0, const float* __restrict__ b1_1)
{
    int enc = blockIdx.y;
    int row = blockIdx.x * 8 + (threadIdx.x >> 5);
    int lane = threadIdx.x & 31;
    if (row >= n) return;
    const __half* __restrict__ g16 = d_g16[enc];
    __half* __restrict__ t16 = d_t16[enc];
    float* zout = z ? z + (size_t)enc * n * 192 : nullptr;
    __half* h16out = enc ? h1 : h0;
    const float* __restrict__ b1 = enc ? b1_1 : b1_0;
    const int* __restrict__ rp = d_rp[enc];
    const int2* __restrict__ edg = d_edge[enc];

    float di = d_dinv[enc][row];
    float sw = di * di;
    uint2 su = reinterpret_cast<const uint2*>(g16 + (size_t)row * 128)[lane];
    float2 s0 = __half22float2(*reinterpret_cast<__half2*>(&su.x));
    float2 s1 = __half22float2(*reinterpret_cast<__half2*>(&su.y));
    float4 acc = make_float4(sw * s0.x, sw * s0.y, sw * s1.x, sw * s1.y);
    int beg = rp[row], end = rp[row + 1];

    float2 a0, a1;
#define ACC128(vv, wv_) \
    a0 = __half22float2(*reinterpret_cast<__half2*>(&vv.x)); \
    a1 = __half22float2(*reinterpret_cast<__half2*>(&vv.y)); \
    acc.x = fmaf(wv_, a0.x, acc.x); acc.y = fmaf(wv_, a0.y, acc.y); \
    acc.z = fmaf(wv_, a1.x, acc.z); acc.w = fmaf(wv_, a1.y, acc.w);

    int u = beg;
    for (; u + 8 <= end; u += 8) {
        int2 E0 = edg[u + 0]; int2 E1 = edg[u + 1];
        int2 E2 = edg[u + 2]; int2 E3 = edg[u + 3];
        int2 E4 = edg[u + 4]; int2 E5 = edg[u + 5];
        int2 E6 = edg[u + 6]; int2 E7 = edg[u + 7];
        uint2 v0 = reinterpret_cast<const uint2*>(g16 + (size_t)E0.x * 128)[lane];
        uint2 v1 = reinterpret_cast<const uint2*>(g16 + (size_t)E1.x * 128)[lane];
        uint2 v2 = reinterpret_cast<const uint2*>(g16 + (size_t)E2.x * 128)[lane];
        uint2 v3 = reinterpret_cast<const uint2*>(g16 + (size_t)E3.x * 128)[lane];
        uint2 v4 = reinterpret_cast<const uint2*>(g16 + (size_t)E4.x * 128)[lane];
        uint2 v5 = reinterpret_cast<const uint2*>(g16 + (size_t)E5.x * 128)[lane];
        uint2 v6 = reinterpret_cast<const uint2*>(g16 + (size_t)E6.x * 128)[lane];
        uint2 v7 = reinterpret_cast<const uint2*>(g16 + (size_t)E7.x * 128)[lane];
        ACC128(v0, __int_as_float(E0.y)) ACC128(v1, __int_as_float(E1.y))
        ACC128(v2, __int_as_float(E2.y)) ACC128(v3, __int_as_float(E3.y))
        ACC128(v4, __int_as_float(E4.y)) ACC128(v5, __int_as_float(E5.y))
        ACC128(v6, __int_as_float(E6.y)) ACC128(v7, __int_as_float(E7.y))
    }
    for (; u < end; u++) {
        int2 E = edg[u];
        uint2 vu = reinterpret_cast<const uint2*>(g16 + (size_t)E.x * 128)[lane];
        ACC128(vu, __int_as_float(E.y))
    }
#undef ACC128

    if (lane < 16) {
        int c = lane * 4;
        float4 o;
        o.x = tanh_fast(acc.x + b1[c + 0]); o.y = tanh_fast(acc.y + b1[c + 1]);
        o.z = tanh_fast(acc.z + b1[c + 2]); o.w = tanh_fast(acc.w + b1[c + 3]);
        if (zout) {
            reinterpret_cast<float4*>(zout + (size_t)row * 192 + 64)[lane] = o;
        } else {
            uint2 hu;
            __half2 q0 = __floats2half2_rn(o.x, o.y);
            __half2 q1 = __floats2half2_rn(o.z, o.w);
            hu.x = *reinterpret_cast<uint32_t*>(&q0);
            hu.y = *reinterpret_cast<uint32_t*>(&q1);
            reinterpret_cast<uint2*>(h16out + (size_t)row * 192 + 64)[lane] = hu;
        }
    } else {
        uint2 tu;
        __half2 q0 = __floats2half2_rn(acc.x, acc.y);
        __half2 q1 = __floats2half2_rn(acc.z, acc.w);
        tu.x = *reinterpret_cast<uint32_t*>(&q0);
        tu.y = *reinterpret_cast<uint32_t*>(&q1);
        reinterpret_cast<uint2*>(t16 + (size_t)row * 64)[lane - 16] = tu;
    }
}

// ------ second hop: warp per row, broadcast edge loads (8-deep) --------------
__global__ void prop64_kernel(int n,
                              float* __restrict__ z, __half* __restrict__ h0, __half* __restrict__ h1,
                              const float* __restrict__ b2_0, const float* __restrict__ b2_1)
{
    int enc = blockIdx.y;
    int row = blockIdx.x * 8 + (threadIdx.x >> 5);
    int lane = threadIdx.x & 31;
    if (row >= n) return;
    const __half* __restrict__ t16 = d_t16[enc];
    float* zout = z ? z + (size_t)enc * n * 192 : nullptr;
    __half* h16out = enc ? h1 : h0;
    const float* __restrict__ b2 = enc ? b2_1 : b2_0;
    const int* __restrict__ rp = d_rp[enc];
    const int2* __restrict__ edg = d_edge[enc];

    float di = d_dinv[enc][row];
    float sw = di * di;
    __half2 sh = reinterpret_cast<const __half2*>(t16 + (size_t)row * 64)[lane];
    float2 s = __half22float2(sh);
    float2 acc = make_float2(sw * s.x, sw * s.y);
    int beg = rp[row], end = rp[row + 1];

    float2 a;
#define ACC64(vv, wv_) \
    a = __half22float2(vv); \
    acc.x = fmaf(wv_, a.x, acc.x); acc.y = fmaf(wv_, a.y, acc.y);

    int u = beg;
    for (; u + 8 <= end; u += 8) {
        int2 E0 = edg[u + 0]; int2 E1 = edg[u + 1];
        int2 E2 = edg[u + 2]; int2 E3 = edg[u + 3];
        int2 E4 = edg[u + 4]; int2 E5 = edg[u + 5];
        int2 E6 = edg[u + 6]; int2 E7 = edg[u + 7];
        __half2 v0 = reinterpret_cast<const __half2*>(t16 + (size_t)E0.x * 64)[lane];
        __half2 v1 = reinterpret_cast<const __half2*>(t16 + (size_t)E1.x * 64)[lane];
        __half2 v2 = reinterpret_cast<const __half2*>(t16 + (size_t)E2.x * 64)[lane];
        __half2 v3 = reinterpret_cast<const __half2*>(t16 + (size_t)E3.x * 64)[lane];
        __half2 v4 = reinterpret_cast<const __half2*>(t16 + (size_t)E4.x * 64)[lane];
        __half2 v5 = reinterpret_cast<const __half2*>(t16 + (size_t)E5.x * 64)[lane];
        __half2 v6 = reinterpret_cast<const __half2*>(t16 + (size_t)E6.x * 64)[lane];
        __half2 v7 = reinterpret_cast<const __half2*>(t16 + (size_t)E7.x * 64)[lane];
        ACC64(v0, __int_as_float(E0.y)) ACC64(v1, __int_as_float(E1.y))
        ACC64(v2, __int_as_float(E2.y)) ACC64(v3, __int_as_float(E3.y))
        ACC64(v4, __int_as_float(E4.y)) ACC64(v5, __int_as_float(E5.y))
        ACC64(v6, __int_as_float(E6.y)) ACC64(v7, __int_as_float(E7.y))
    }
    for (; u < end; u++) {
        int2 E = edg[u];
        __half2 vh = reinterpret_cast<const __half2*>(t16 + (size_t)E.x * 64)[lane];
        ACC64(vh, __int_as_float(E.y))
    }
#undef ACC64

    int c = lane * 2;
    float2 o;
    o.x = tanh_fast(acc.x + b2[c + 0]);
    o.y = tanh_fast(acc.y + b2[c + 1]);
    if (zout) {
        reinterpret_cast<float2*>(zout + (size_t)row * 192 + 128)[lane] = o;
    } else {
        reinterpret_cast<__half2*>(h16out + (size_t)row * 192 + 128)[lane] = __floats2half2_rn(o.x, o.y);
    }
}

extern "C" void kernel_launch(void* const* d_in, const int* in_sizes, int n_in,
                              void* d_out, int out_size)
{
    const float* x = (const float*)d_in[0];
    const void* ei = d_in[1];
    int n = in_sizes[0] / 256;
    int e = in_sizes[1] / 2;
    if (n > NN) n = NN;
    if (e > EE) e = EE;

    static cudaStream_t s2 = nullptr;
    static cudaEvent_t evFork = nullptr, evJoin = nullptr;
    if (s2 == nullptr) {
        cudaStreamCreateWithFlags(&s2, cudaStreamNonBlocking);
        cudaEventCreateWithFlags(&evFork, cudaEventDisableTiming);
        cudaEventCreateWithFlags(&evJoin, cudaEventDisableTiming);
    }

    __half* x16 = nullptr; __half* hA0; __half* hA1; __half* hB0; __half* hB1;
    cudaGetSymbolAddress((void**)&x16, d_x16);
    cudaGetSymbolAddress((void**)&hA0, d_hA);
    hA1 = hA0 + (size_t)NN * 192;
    cudaGetSymbolAddress((void**)&hB0, d_hB);
    hB1 = hB0 + (size_t)NN * 192;

    const float* b1_0 = (const float*)d_in[3];
    const float* b2_0 = (const float*)d_in[5];
    const float* b3_0 = (const float*)d_in[7];
    const float* b1_1 = (const float*)d_in[9];
    const float* b2_1 = (const float*)d_in[11];
    const float* b3_1 = (const float*)d_in[13];
    float* z = (float*)d_out;

    int smem_gemm = 2 * BUF_CH * 2;
    cudaFuncSetAttribute(gemm_mma_kernel, cudaFuncAttributeMaxDynamicSharedMemorySize, smem_gemm);

    dim3 ggrid((n + 127) / 128, 2);
    dim3 pgrid((n + 7) / 8, 2);

    WPtrs wp;
    for (int i = 0; i < 6; i++) wp.w[i] = (const float*)d_in[2 + (i / 3) * 6 + (i % 3) * 2];

    // ---- fork: side stream does conversions + layer-1 GEMM (graph-independent)
    cudaEventRecord(evFork, 0);
    cudaStreamWaitEvent(s2, evFork, 0);
    convx_kernel<<<(n * 64 + 255) / 256, 256, 0, s2>>>(x, n * 64);
    convw_all_kernel<<<dim3((192 * 256 + 255) / 256, 6), 256, 0, s2>>>(wp);
    gemm_mma_kernel<<<ggrid, 256, smem_gemm, s2>>>(x16, x16, 0, 256, n, b1_0, b1_1, nullptr, hA0, hA1);
    cudaEventRecord(evJoin, s2);

    // ---- main stream: graph build chain
    zero_detect_kernel<<<(n + 255) / 256, 256>>>((const int*)ei, n);
    hist_kernel<<<(e + 255) / 256, 256>>>(ei, e);
    int nchunks = (n + 511) / 512;
    dim3 sgrid(nchunks, 2);
    scan1_kernel<<<sgrid, 512>>>(n);
    scan2_kernel<<<1, 1024>>>(nchunks, n);
    scan3_kernel<<<sgrid, 512>>>(n);
    place_kernel<<<(e + 255) / 256, 256>>>(e);

    // ---- join
    cudaStreamWaitEvent(0, evJoin, 0);

    prop_fused_kernel<<<pgrid, 256>>>(n, nullptr, hA0, hA1, b1_0 + 64, b1_1 + 64);
    prop64_kernel<<<pgrid, 256>>>(n, nullptr, hA0, hA1, b1_0 + 128, b1_1 + 128);
    // layer 2
    gemm_mma_kernel<<<ggrid, 256, smem_gemm>>>(hA0, hA1, 1, 192, n, b2_0, b2_1, nullptr, hB0, hB1);
    prop_fused_kernel<<<pgrid, 256>>>(n, nullptr, hB0, hB1, b2_0 + 64, b2_1 + 64);
    prop64_kernel<<<pgrid, 256>>>(n, nullptr, hB0, hB1, b2_0 + 128, b2_1 + 128);
    // layer 3 -> z (fp32 output)
    gemm_mma_kernel<<<ggrid, 256, smem_gemm>>>(hB0, hB1, 2, 192, n, b3_0, b3_1, z, nullptr, nullptr);
    prop_fused_kernel<<<pgrid, 256>>>(n, z, nullptr, nullptr, b3_0 + 64, b3_1 + 64);
    prop64_kernel<<<pgrid, 256>>>(n, z, nullptr, nullptr, b3_0 + 128, b3_1 + 128);
}

// round 15
// speedup vs baseline: 1.0169x; 1.0017x over previous
#include <cuda_runtime.h>
#include <cuda_fp16.h>
#include <math.h>
#include <stdint.h>

#define NN 50000
#define EE 800000

// ---------------- scratch (static __device__, allocation-free) ----------------
__device__ __half d_x16[NN * 256];
__device__ __half d_hA[2][NN * 192];
__device__ __half d_hB[2][NN * 192];
__device__ __half d_g16[2][NN * 128];
__device__ __half d_t16[2][NN * 64];
__device__ __half d_w16all[6][192 * 256];
__device__ int   d_cnt[2][NN];
__device__ int   d_rp[2][NN + 1];
__device__ int   d_cur[2][NN];
__device__ int2  d_edge[2][EE];
__device__ int2  d_sd[EE];
__device__ float d_dinv[2][NN];
__device__ int   d_bsum[2][512];
__device__ int   d_boff[2][512];
__device__ int   d_flag[1];

__device__ __forceinline__ uint32_t smem_u32(const void* p) {
    uint32_t a;
    asm("{ .reg .u64 t; cvta.to.shared.u64 t, %1; cvt.u32.u64 %0, t; }" : "=r"(a) : "l"(p));
    return a;
}
__device__ __forceinline__ float tanh_fast(float x) {
    float y;
    asm("tanh.approx.f32 %0, %1;" : "=f"(y) : "f"(x));
    return y;
}
__device__ __forceinline__ void cp_async16(uint32_t dst, const void* src, uint32_t src_bytes) {
    asm volatile("cp.async.cg.shared.global [%0], [%1], 16, %2;"
                 :: "r"(dst), "l"(src), "r"(src_bytes) : "memory");
}
#define CP_COMMIT() asm volatile("cp.async.commit_group;" ::: "memory")
#define CP_WAIT(N)  asm volatile("cp.async.wait_group %0;" :: "n"(N) : "memory")

// ---------------- graph build ----------------
__global__ void detect_kernel(const int* ei32) {
    __shared__ int any;
    if (threadIdx.x == 0) any = 0;
    __syncthreads();
    if (ei32[2 * threadIdx.x + 1] != 0) atomicExch(&any, 1);
    __syncthreads();
    if (threadIdx.x == 0) d_flag[0] = (any == 0) ? 1 : 0;
}

__device__ __forceinline__ void load_edge(const void* ei, int e, int t, int& s, int& d) {
    if (d_flag[0]) {
        const long long* p = (const long long*)ei;
        s = (int)p[t]; d = (int)p[e + t];
    } else {
        const int* p = (const int*)ei;
        s = p[t]; d = p[e + t];
    }
}

__global__ void hist_kernel(const void* ei, int e) {
    int t = blockIdx.x * blockDim.x + threadIdx.x;
    if (t >= e) return;
    int s, d;
    load_edge(ei, e, t, s, d);
    d_sd[t] = make_int2(s, d);
    atomicAdd(&d_cnt[0][d], 1);
    atomicAdd(&d_cnt[1][s], 1);
}

__global__ void scan1_kernel(int n) {
    int g = blockIdx.y;
    int i = blockIdx.x * 512 + threadIdx.x;
    __shared__ int sh[512];
    sh[threadIdx.x] = (i < n) ? d_cnt[g][i] : 0;
    __syncthreads();
    for (int off = 256; off > 0; off >>= 1) {
        if (threadIdx.x < off) sh[threadIdx.x] += sh[threadIdx.x + off];
        __syncthreads();
    }
    if (threadIdx.x == 0) d_bsum[g][blockIdx.x] = sh[0];
}

__global__ void scan2_kernel(int nchunks, int n) {
    int t = threadIdx.x;
    int g = t >> 9, i = t & 511;
    __shared__ int sh[1024];
    int v = (i < nchunks) ? d_bsum[g][i] : 0;
    int orig = v;
    sh[t] = v;
    __syncthreads();
    for (int off = 1; off < 512; off <<= 1) {
        int add = (i >= off) ? sh[t - off] : 0;
        __syncthreads();
        sh[t] += add;
        __syncthreads();
    }
    d_boff[g][i] = sh[t] - orig;
    if (i == 511) d_rp[g][n] = sh[t];
}

__global__ void scan3_kernel(int n) {
    int g = blockIdx.y;
    int t = threadIdx.x;
    int i = blockIdx.x * 512 + t;
    __shared__ int sh[512];
    int c = (i < n) ? d_cnt[g][i] : 0;
    sh[t] = c;
    __syncthreads();
    for (int off = 1; off < 512; off <<= 1) {
        int add = (t >= off) ? sh[t - off] : 0;
        __syncthreads();
        sh[t] += add;
        __syncthreads();
    }
    if (i < n) {
        int excl = sh[t] - c + d_boff[g][blockIdx.x];
        d_rp[g][i] = excl;
        d_cur[g][i] = excl;
        d_dinv[g][i] = rsqrtf((float)c + 1.0f);
    }
}

__global__ void place_kernel(int e) {
    int t = blockIdx.x * blockDim.x + threadIdx.x;
    if (t >= e) return;
    int2 sd = d_sd[t];
    int s = sd.x, d = sd.y;
    float w0 = d_dinv[0][s] * d_dinv[0][d];
    int p0 = atomicAdd(&d_cur[0][d], 1);
    d_edge[0][p0] = make_int2(s, __float_as_int(w0));
    float w1 = d_dinv[1][s] * d_dinv[1][d];
    int p1 = atomicAdd(&d_cur[1][s], 1);
    d_edge[1][p1] = make_int2(d, __float_as_int(w1));
}

// ---------------- conversions ----------------
__global__ void convx_kernel(const float* __restrict__ x, int n4) {
    int i = blockIdx.x * blockDim.x + threadIdx.x;
    if (i >= n4) return;
    float4 v = reinterpret_cast<const float4*>(x)[i];
    reinterpret_cast<__half2*>(d_x16)[i * 2] = __floats2half2_rn(v.x, v.y);
    reinterpret_cast<__half2*>(d_x16)[i * 2 + 1] = __floats2half2_rn(v.z, v.w);
}

struct WPtrs { const float* w[6]; };

__global__ void convw_all_kernel(WPtrs wp) {
    int s = blockIdx.y;
    int din = ((s % 3) == 0) ? 256 : 192;
    int idx = blockIdx.x * 256 + threadIdx.x;
    if (idx >= 192 * din) return;
    int r = idx / din, k = idx - r * din;
    d_w16all[s][r * 256 + k] = __float2half(wp.w[s][((r >> 6) * din + k) * 64 + (r & 63)]);
}

// ---------------- mma.sync GEMM, double-buffered cp.async ----------------
#define KC 64
#define SKA 72
#define A_CH (128 * SKA)
#define B_CH (192 * SKA)
#define BUF_CH (A_CH + B_CH)

__global__ void __launch_bounds__(256) gemm_mma_kernel(
    const __half* __restrict__ H0, const __half* __restrict__ H1,
    int wslot, int din, int n,
    const float* __restrict__ bias0, const float* __restrict__ bias1,
    float* __restrict__ z, __half* __restrict__ h0, __half* __restrict__ h1)
{
    int enc = blockIdx.y;
    const __half* __restrict__ H = enc ? H1 : H0;
    const float* __restrict__ bias = enc ? bias1 : bias0;
    float* zout = z ? z + (size_t)enc * n * 192 : nullptr;
    __half* h16out = enc ? h1 : h0;
    const __half* __restrict__ Wm = d_w16all[enc * 3 + wslot];
    __half* __restrict__ g16 = d_g16[enc];

    extern __shared__ __half smh[];
    int tid = threadIdx.x, wid = tid >> 5, lane = tid & 31;
    int row0 = blockIdx.x * 128;
    int nk = din / KC;

    uint32_t sbase = smem_u32(smh);

    auto load_chunk = [&](int b, int kc) {
        uint32_t abuf = sbase + (uint32_t)(b * BUF_CH) * 2u;
        uint32_t bbuf = abuf + (uint32_t)A_CH * 2u;
        int k0 = kc * KC;
#pragma unroll
        for (int i = 0; i < 4; i++) {
            int idx = tid + 256 * i;
            int r = idx >> 3, c16 = idx & 7;
            const __half* src = H + (size_t)(row0 + r) * din + k0 + c16 * 8;
            uint32_t ok = (row0 + r < n) ? 16u : 0u;
            cp_async16(abuf + (uint32_t)(r * SKA + c16 * 8) * 2u, src, ok);
        }
#pragma unroll
        for (int i = 0; i < 6; i++) {
            int idx = tid + 256 * i;
            int r = idx >> 3, c16 = idx & 7;
            const __half* src = Wm + (size_t)r * 256 + k0 + c16 * 8;
            cp_async16(bbuf + (uint32_t)(r * SKA + c16 * 8) * 2u, src, 16u);
        }
        CP_COMMIT();
    };

    float acc[24][4];
#pragma unroll
    for (int i = 0; i < 24; i++)
#pragma unroll
        for (int j = 0; j < 4; j++) acc[i][j] = 0.f;

    int mrow = wid * 16;
    uint32_t a_off = (uint32_t)((mrow + (lane & 15)) * SKA + (lane >> 4) * 8) * 2u;
    uint32_t b_off = (uint32_t)((((lane >> 4) * 8 + (lane & 7)) * SKA) + ((lane >> 3) & 1) * 8) * 2u;
    uint32_t b_step2 = (uint32_t)(16 * SKA) * 2u;

    load_chunk(0, 0);

    for (int c = 0; c < nk; c++) {
        if (c + 1 < nk) {
            load_chunk((c + 1) & 1, c + 1);
            CP_WAIT(1);
        } else {
            CP_WAIT(0);
        }
        __syncthreads();
        uint32_t abuf = sbase + (uint32_t)((c & 1) * BUF_CH) * 2u;
        uint32_t bbuf = abuf + (uint32_t)A_CH * 2u;
#pragma unroll
        for (int ks = 0; ks < 4; ks++) {
            uint32_t a0, a1, a2, a3;
            asm volatile("ldmatrix.sync.aligned.m8n8.x4.shared.b16 {%0,%1,%2,%3}, [%4];"
                : "=r"(a0), "=r"(a1), "=r"(a2), "=r"(a3) : "r"(abuf + a_off + ks * 32));
            uint32_t bb = bbuf + b_off + ks * 32;
#pragma unroll
            for (int nt2 = 0; nt2 < 12; nt2++) {
                uint32_t b0r, b1r, b2r, b3r;
                asm volatile("ldmatrix.sync.aligned.m8n8.x4.shared.b16 {%0,%1,%2,%3}, [%4];"
                    : "=r"(b0r), "=r"(b1r), "=r"(b2r), "=r"(b3r) : "r"(bb));
                asm volatile("mma.sync.aligned.m16n8k16.row.col.f32.f16.f16.f32 "
                    "{%0,%1,%2,%3}, {%4,%5,%6,%7}, {%8,%9}, {%0,%1,%2,%3};"
                    : "+f"(acc[2*nt2][0]), "+f"(acc[2*nt2][1]), "+f"(acc[2*nt2][2]), "+f"(acc[2*nt2][3])
                    : "r"(a0), "r"(a1), "r"(a2), "r"(a3), "r"(b0r), "r"(b1r));
                asm volatile("mma.sync.aligned.m16n8k16.row.col.f32.f16.f16.f32 "
                    "{%0,%1,%2,%3}, {%4,%5,%6,%7}, {%8,%9}, {%0,%1,%2,%3};"
                    : "+f"(acc[2*nt2+1][0]), "+f"(acc[2*nt2+1][1]), "+f"(acc[2*nt2+1][2]), "+f"(acc[2*nt2+1][3])
                    : "r"(a0), "r"(a1), "r"(a2), "r"(a3), "r"(b2r), "r"(b3r));
                bb += b_step2;
            }
        }
        __syncthreads();
    }

    int r0 = row0 + mrow + (lane >> 2);
    int r1 = r0 + 8;
#pragma unroll
    for (int nt = 0; nt < 24; nt++) {
        int c = nt * 8 + (lane & 3) * 2;
        if (c < 64) {
            float vb0 = bias[c], vb1 = bias[c + 1];
            float o00 = tanh_fast(acc[nt][0] + vb0), o01 = tanh_fast(acc[nt][1] + vb1);
            float o10 = tanh_fast(acc[nt][2] + vb0), o11 = tanh_fast(acc[nt][3] + vb1);
            if (zout) {
                if (r0 < n) *reinterpret_cast<float2*>(zout + (size_t)r0 * 192 + c) = make_float2(o00, o01);
                if (r1 < n) *reinterpret_cast<float2*>(zout + (size_t)r1 * 192 + c) = make_float2(o10, o11);
            } else {
                if (r0 < n) *reinterpret_cast<__half2*>(h16out + (size_t)r0 * 192 + c) = __floats2half2_rn(o00, o01);
                if (r1 < n) *reinterpret_cast<__half2*>(h16out + (size_t)r1 * 192 + c) = __floats2half2_rn(o10, o11);
            }
        } else {
            int cg = c - 64;
            if (r0 < n) *reinterpret_cast<__half2*>(g16 + (size_t)r0 * 128 + cg) = __floats2half2_rn(acc[nt][0], acc[nt][1]);
            if (r1 < n) *reinterpret_cast<__half2*>(g16 + (size_t)r1 * 128 + cg) = __floats2half2_rn(acc[nt][2], acc[nt][3]);
        }
    }
}

// ------ fused prop over 128 cols: warp per row, broadcast edge loads (8-deep)
__global__ void prop_fused_kernel(int n,
                                  float* __restrict__ z, __half* __restrict__ h0, __half* __restrict__ h1,
                                  const float* __restrict__ b1_0, const float* __restrict__ b1_1)
{
    int enc = blockIdx.y;
    int row = blockIdx.x * 8 + (threadIdx.x >> 5);
    int lane = threadIdx.x & 31;
    if (row >= n) return;
    const __half* __restrict__ g16 = d_g16[enc];
    __half* __restrict__ t16 = d_t16[enc];
    float* zout = z ? z + (size_t)enc * n * 192 : nullptr;
    __half* h16out = enc ? h1 : h0;
    const float* __restrict__ b1 = enc ? b1_1 : b1_0;
    const int* __restrict__ rp = d_rp[enc];
    const int2* __restrict__ edg = d_edge[enc];

    float di = d_dinv[enc][row];
    float sw = di * di;
    uint2 su = reinterpret_cast<const uint2*>(g16 + (size_t)row * 128)[lane];
    float2 s0 = __half22float2(*reinterpret_cast<__half2*>(&su.x));
    float2 s1 = __half22float2(*reinterpret_cast<__half2*>(&su.y));
    float4 acc = make_float4(sw * s0.x, sw * s0.y, sw * s1.x, sw * s1.y);
    int beg = rp[row], end = rp[row + 1];

    float2 a0, a1;
#define ACC128(vv, wv_) \
    a0 = __half22float2(*reinterpret_cast<__half2*>(&vv.x)); \
    a1 = __half22float2(*reinterpret_cast<__half2*>(&vv.y)); \
    acc.x = fmaf(wv_, a0.x, acc.x); acc.y = fmaf(wv_, a0.y, acc.y); \
    acc.z = fmaf(wv_, a1.x, acc.z); acc.w = fmaf(wv_, a1.y, acc.w);

    int u = beg;
    for (; u + 8 <= end; u += 8) {
        int2 E0 = edg[u + 0]; int2 E1 = edg[u + 1];
        int2 E2 = edg[u + 2]; int2 E3 = edg[u + 3];
        int2 E4 = edg[u + 4]; int2 E5 = edg[u + 5];
        int2 E6 = edg[u + 6]; int2 E7 = edg[u + 7];
        uint2 v0 = reinterpret_cast<const uint2*>(g16 + (size_t)E0.x * 128)[lane];
        uint2 v1 = reinterpret_cast<const uint2*>(g16 + (size_t)E1.x * 128)[lane];
        uint2 v2 = reinterpret_cast<const uint2*>(g16 + (size_t)E2.x * 128)[lane];
        uint2 v3 = reinterpret_cast<const uint2*>(g16 + (size_t)E3.x * 128)[lane];
        uint2 v4 = reinterpret_cast<const uint2*>(g16 + (size_t)E4.x * 128)[lane];
        uint2 v5 = reinterpret_cast<const uint2*>(g16 + (size_t)E5.x * 128)[lane];
        uint2 v6 = reinterpret_cast<const uint2*>(g16 + (size_t)E6.x * 128)[lane];
        uint2 v7 = reinterpret_cast<const uint2*>(g16 + (size_t)E7.x * 128)[lane];
        ACC128(v0, __int_as_float(E0.y)) ACC128(v1, __int_as_float(E1.y))
        ACC128(v2, __int_as_float(E2.y)) ACC128(v3, __int_as_float(E3.y))
        ACC128(v4, __int_as_float(E4.y)) ACC128(v5, __int_as_float(E5.y))
        ACC128(v6, __int_as_float(E6.y)) ACC128(v7, __int_as_float(E7.y))
    }
    for (; u < end; u++) {
        int2 E = edg[u];
        uint2 vu = reinterpret_cast<const uint2*>(g16 + (size_t)E.x * 128)[lane];
        ACC128(vu, __int_as_float(E.y))
    }
#undef ACC128

    if (lane < 16) {
        int c = lane * 4;
        float4 o;
        o.x = tanh_fast(acc.x + b1[c + 0]); o.y = tanh_fast(acc.y + b1[c + 1]);
        o.z = tanh_fast(acc.z + b1[c + 2]); o.w = tanh_fast(acc.w + b1[c + 3]);
        if (zout) {
            reinterpret_cast<float4*>(zout + (size_t)row * 192 + 64)[lane] = o;
        } else {
            uint2 hu;
            __half2 q0 = __floats2half2_rn(o.x, o.y);
            __half2 q1 = __floats2half2_rn(o.z, o.w);
            hu.x = *reinterpret_cast<uint32_t*>(&q0);
            hu.y = *reinterpret_cast<uint32_t*>(&q1);
            reinterpret_cast<uint2*>(h16out + (size_t)row * 192 + 64)[lane] = hu;
        }
    } else {
        uint2 tu;
        __half2 q0 = __floats2half2_rn(acc.x, acc.y);
        __half2 q1 = __floats2half2_rn(acc.z, acc.w);
        tu.x = *reinterpret_cast<uint32_t*>(&q0);
        tu.y = *reinterpret_cast<uint32_t*>(&q1);
        reinterpret_cast<uint2*>(t16 + (size_t)row * 64)[lane - 16] = tu;
    }
}

// ------ second hop: warp per row, broadcast edge loads (8-deep) --------------
__global__ void prop64_kernel(int n,
                              float* __restrict__ z, __half* __restrict__ h0, __half* __restrict__ h1,
                              const float* __restrict__ b2_0, const float* __restrict__ b2_1)
{
    int enc = blockIdx.y;
    int row = blockIdx.x * 8 + (threadIdx.x >> 5);
    int lane = threadIdx.x & 31;
    if (row >= n) return;
    const __half* __restrict__ t16 = d_t16[enc];
    float* zout = z ? z + (size_t)enc * n * 192 : nullptr;
    __half* h16out = enc ? h1 : h0;
    const float* __restrict__ b2 = enc ? b2_1 : b2_0;
    const int* __restrict__ rp = d_rp[enc];
    const int2* __restrict__ edg = d_edge[enc];

    float di = d_dinv[enc][row];
    float sw = di * di;
    __half2 sh = reinterpret_cast<const __half2*>(t16 + (size_t)row * 64)[lane];
    float2 s = __half22float2(sh);
    float2 acc = make_float2(sw * s.x, sw * s.y);
    int beg = rp[row], end = rp[row + 1];

    float2 a;
#define ACC64(vv, wv_) \
    a = __half22float2(vv); \
    acc.x = fmaf(wv_, a.x, acc.x); acc.y = fmaf(wv_, a.y, acc.y);

    int u = beg;
    for (; u + 8 <= end; u += 8) {
        int2 E0 = edg[u + 0]; int2 E1 = edg[u + 1];
        int2 E2 = edg[u + 2]; int2 E3 = edg[u + 3];
        int2 E4 = edg[u + 4]; int2 E5 = edg[u + 5];
        int2 E6 = edg[u + 6]; int2 E7 = edg[u + 7];
        __half2 v0 = reinterpret_cast<const __half2*>(t16 + (size_t)E0.x * 64)[lane];
        __half2 v1 = reinterpret_cast<const __half2*>(t16 + (size_t)E1.x * 64)[lane];
        __half2 v2 = reinterpret_cast<const __half2*>(t16 + (size_t)E2.x * 64)[lane];
        __half2 v3 = reinterpret_cast<const __half2*>(t16 + (size_t)E3.x * 64)[lane];
        __half2 v4 = reinterpret_cast<const __half2*>(t16 + (size_t)E4.x * 64)[lane];
        __half2 v5 = reinterpret_cast<const __half2*>(t16 + (size_t)E5.x * 64)[lane];
        __half2 v6 = reinterpret_cast<const __half2*>(t16 + (size_t)E6.x * 64)[lane];
        __half2 v7 = reinterpret_cast<const __half2*>(t16 + (size_t)E7.x * 64)[lane];
        ACC64(v0, __int_as_float(E0.y)) ACC64(v1, __int_as_float(E1.y))
        ACC64(v2, __int_as_float(E2.y)) ACC64(v3, __int_as_float(E3.y))
        ACC64(v4, __int_as_float(E4.y)) ACC64(v5, __int_as_float(E5.y))
        ACC64(v6, __int_as_float(E6.y)) ACC64(v7, __int_as_float(E7.y))
    }
    for (; u < end; u++) {
        int2 E = edg[u];
        __half2 vh = reinterpret_cast<const __half2*>(t16 + (size_t)E.x * 64)[lane];
        ACC64(vh, __int_as_float(E.y))
    }
#undef ACC64

    int c = lane * 2;
    float2 o;
    o.x = tanh_fast(acc.x + b2[c + 0]);
    o.y = tanh_fast(acc.y + b2[c + 1]);
    if (zout) {
        reinterpret_cast<float2*>(zout + (size_t)row * 192 + 128)[lane] = o;
    } else {
        reinterpret_cast<__half2*>(h16out + (size_t)row * 192 + 128)[lane] = __floats2half2_rn(o.x, o.y);
    }
}

extern "C" void kernel_launch(void* const* d_in, const int* in_sizes, int n_in,
                              void* d_out, int out_size)
{
    const float* x = (const float*)d_in[0];
    const void* ei = d_in[1];
    int n = in_sizes[0] / 256;
    int e = in_sizes[1] / 2;
    if (n > NN) n = NN;
    if (e > EE) e = EE;

    static cudaStream_t s2 = nullptr;
    static cudaEvent_t evFork = nullptr, evJoin = nullptr, evDet = nullptr;
    if (s2 == nullptr) {
        cudaStreamCreateWithFlags(&s2, cudaStreamNonBlocking);
        cudaEventCreateWithFlags(&evFork, cudaEventDisableTiming);
        cudaEventCreateWithFlags(&evJoin, cudaEventDisableTiming);
        cudaEventCreateWithFlags(&evDet, cudaEventDisableTiming);
    }

    __half* x16 = nullptr; __half* hA0; __half* hA1; __half* hB0; __half* hB1;
    cudaGetSymbolAddress((void**)&x16, d_x16);
    cudaGetSymbolAddress((void**)&hA0, d_hA);
    hA1 = hA0 + (size_t)NN * 192;
    cudaGetSymbolAddress((void**)&hB0, d_hB);
    hB1 = hB0 + (size_t)NN * 192;
    int* cnt_ptr = nullptr;
    cudaGetSymbolAddress((void**)&cnt_ptr, d_cnt);

    const float* b1_0 = (const float*)d_in[3];
    const float* b2_0 = (const float*)d_in[5];
    const float* b3_0 = (const float*)d_in[7];
    const float* b1_1 = (const float*)d_in[9];
    const float* b2_1 = (const float*)d_in[11];
    const float* b3_1 = (const float*)d_in[13];
    float* z = (float*)d_out;

    int smem_gemm = 2 * BUF_CH * 2;
    cudaFuncSetAttribute(gemm_mma_kernel, cudaFuncAttributeMaxDynamicSharedMemorySize, smem_gemm);

    dim3 ggrid((n + 127) / 128, 2);
    dim3 pgrid((n + 7) / 8, 2);

    WPtrs wp;
    for (int i = 0; i < 6; i++) wp.w[i] = (const float*)d_in[2 + (i / 3) * 6 + (i % 3) * 2];

    // ---- fork: side stream does dtype-detect + conversions + layer-1 GEMM
    cudaEventRecord(evFork, 0);
    cudaStreamWaitEvent(s2, evFork, 0);
    detect_kernel<<<1, 256, 0, s2>>>((const int*)ei);
    cudaEventRecord(evDet, s2);
    convx_kernel<<<(n * 64 + 255) / 256, 256, 0, s2>>>(x, n * 64);
    convw_all_kernel<<<dim3((192 * 256 + 255) / 256, 6), 256, 0, s2>>>(wp);
    gemm_mma_kernel<<<ggrid, 256, smem_gemm, s2>>>(x16, x16, 0, 256, n, b1_0, b1_1, nullptr, hA0, hA1);
    cudaEventRecord(evJoin, s2);

    // ---- main stream: memset d_cnt (parallel with detect), then build chain
    cudaMemsetAsync(cnt_ptr, 0, sizeof(int) * 2 * NN, 0);
    cudaStreamWaitEvent(0, evDet, 0);
    hist_kernel<<<(e + 255) / 256, 256>>>(ei, e);
    int nchunks = (n + 511) / 512;
    dim3 sgrid(nchunks, 2);
    scan1_kernel<<<sgrid, 512>>>(n);
    scan2_kernel<<<1, 1024>>>(nchunks, n);
    scan3_kernel<<<sgrid, 512>>>(n);
    place_kernel<<<(e + 255) / 256, 256>>>(e);

    // ---- join
    cudaStreamWaitEvent(0, evJoin, 0);

    prop_fused_kernel<<<pgrid, 256>>>(n, nullptr, hA0, hA1, b1_0 + 64, b1_1 + 64);
    prop64_kernel<<<pgrid, 256>>>(n, nullptr, hA0, hA1, b1_0 + 128, b1_1 + 128);
    // layer 2
    gemm_mma_kernel<<<ggrid, 256, smem_gemm>>>(hA0, hA1, 1, 192, n, b2_0, b2_1, nullptr, hB0, hB1);
    prop_fused_kernel<<<pgrid, 256>>>(n, nullptr, hB0, hB1, b2_0 + 64, b2_1 + 64);
    prop64_kernel<<<pgrid, 256>>>(n, nullptr, hB0, hB1, b2_0 + 128, b2_1 + 128);
    // layer 3 -> z (fp32 output)
    gemm_mma_kernel<<<ggrid, 256, smem_gemm>>>(hB0, hB1, 2, 192, n, b3_0, b3_1, z, nullptr, nullptr);
    prop_fused_kernel<<<pgrid, 256>>>(n, z, nullptr, nullptr, b3_0 + 64, b3_1 + 64);
    prop64_kernel<<<pgrid, 256>>>(n, z, nullptr, nullptr, b3_0 + 128, b3_1 + 128);
}

// round 16
// speedup vs baseline: 1.0244x; 1.0074x over previous
#include <cuda_runtime.h>
#include <cuda_fp16.h>
#include <math.h>
#include <stdint.h>

#define NN 50000
#define EE 800000

// ---------------- scratch (static __device__, allocation-free) ----------------
__device__ __half d_x16[NN * 256];
__device__ __half d_hA[2][NN * 192];
__device__ __half d_hB[2][NN * 192];
__device__ __half d_g16[2][NN * 128];
__device__ __half d_t16[2][NN * 64];
__device__ __half d_w16all[6][192 * 256];
__device__ int   d_cnt[2][NN];
__device__ int   d_rp[2][NN + 1];
__device__ int   d_cur[2][NN];
__device__ int2  d_edge[2][EE];
__device__ int2  d_sd[EE];
__device__ float d_dinv[2][NN];
__device__ int   d_bsum[2][512];
__device__ int   d_boff[2][512];
__device__ int   d_flag[1];

__device__ __forceinline__ uint32_t smem_u32(const void* p) {
    uint32_t a;
    asm("{ .reg .u64 t; cvta.to.shared.u64 t, %1; cvt.u32.u64 %0, t; }" : "=r"(a) : "l"(p));
    return a;
}
__device__ __forceinline__ float tanh_fast(float x) {
    float y;
    asm("tanh.approx.f32 %0, %1;" : "=f"(y) : "f"(x));
    return y;
}
__device__ __forceinline__ void cp_async16(uint32_t dst, const void* src, uint32_t src_bytes) {
    asm volatile("cp.async.cg.shared.global [%0], [%1], 16, %2;"
                 :: "r"(dst), "l"(src), "r"(src_bytes) : "memory");
}
#define CP_COMMIT() asm volatile("cp.async.commit_group;" ::: "memory")
#define CP_WAIT(N)  asm volatile("cp.async.wait_group %0;" :: "n"(N) : "memory")

// ---------------- graph build ----------------
__global__ void detect_kernel(const int* ei32) {
    __shared__ int any;
    if (threadIdx.x == 0) any = 0;
    __syncthreads();
    if (ei32[2 * threadIdx.x + 1] != 0) atomicExch(&any, 1);
    __syncthreads();
    if (threadIdx.x == 0) d_flag[0] = (any == 0) ? 1 : 0;
}

__device__ __forceinline__ void load_edge(const void* ei, int e, int t, int& s, int& d) {
    if (d_flag[0]) {
        const long long* p = (const long long*)ei;
        s = (int)p[t]; d = (int)p[e + t];
    } else {
        const int* p = (const int*)ei;
        s = p[t]; d = p[e + t];
    }
}

__global__ void hist_kernel(const void* ei, int e) {
    int t = blockIdx.x * blockDim.x + threadIdx.x;
    if (t >= e) return;
    int s, d;
    load_edge(ei, e, t, s, d);
    d_sd[t] = make_int2(s, d);
    atomicAdd(&d_cnt[0][d], 1);
    atomicAdd(&d_cnt[1][s], 1);
}

__global__ void scan1_kernel(int n) {
    int g = blockIdx.y;
    int i = blockIdx.x * 512 + threadIdx.x;
    __shared__ int sh[512];
    sh[threadIdx.x] = (i < n) ? d_cnt[g][i] : 0;
    __syncthreads();
    for (int off = 256; off > 0; off >>= 1) {
        if (threadIdx.x < off) sh[threadIdx.x] += sh[threadIdx.x + off];
        __syncthreads();
    }
    if (threadIdx.x == 0) d_bsum[g][blockIdx.x] = sh[0];
}

__global__ void scan2_kernel(int nchunks, int n) {
    int t = threadIdx.x;
    int g = t >> 9, i = t & 511;
    __shared__ int sh[1024];
    int v = (i < nchunks) ? d_bsum[g][i] : 0;
    int orig = v;
    sh[t] = v;
    __syncthreads();
    for (int off = 1; off < 512; off <<= 1) {
        int add = (i >= off) ? sh[t - off] : 0;
        __syncthreads();
        sh[t] += add;
        __syncthreads();
    }
    d_boff[g][i] = sh[t] - orig;
    if (i == 511) d_rp[g][n] = sh[t];
}

__global__ void scan3_kernel(int n) {
    int g = blockIdx.y;
    int t = threadIdx.x;
    int i = blockIdx.x * 512 + t;
    __shared__ int sh[512];
    int c = (i < n) ? d_cnt[g][i] : 0;
    sh[t] = c;
    __syncthreads();
    for (int off = 1; off < 512; off <<= 1) {
        int add = (t >= off) ? sh[t - off] : 0;
        __syncthreads();
        sh[t] += add;
        __syncthreads();
    }
    if (i < n) {
        int excl = sh[t] - c + d_boff[g][blockIdx.x];
        d_rp[g][i] = excl;
        d_cur[g][i] = excl;
        d_dinv[g][i] = rsqrtf((float)c + 1.0f);
    }
}

__global__ void place_kernel(int e) {
    int t = blockIdx.x * blockDim.x + threadIdx.x;
    if (t >= e) return;
    int2 sd = d_sd[t];
    int s = sd.x, d = sd.y;
    float w0 = d_dinv[0][s] * d_dinv[0][d];
    int p0 = atomicAdd(&d_cur[0][d], 1);
    d_edge[0][p0] = make_int2(s, __float_as_int(w0));
    float w1 = d_dinv[1][s] * d_dinv[1][d];
    int p1 = atomicAdd(&d_cur[1][s], 1);
    d_edge[1][p1] = make_int2(d, __float_as_int(w1));
}

// ---------------- conversions ----------------
__global__ void convx_kernel(const float* __restrict__ x, int n4) {
    int i = blockIdx.x * blockDim.x + threadIdx.x;
    if (i >= n4) return;
    float4 v = reinterpret_cast<const float4*>(x)[i];
    reinterpret_cast<__half2*>(d_x16)[i * 2] = __floats2half2_rn(v.x, v.y);
    reinterpret_cast<__half2*>(d_x16)[i * 2 + 1] = __floats2half2_rn(v.z, v.w);
}

struct WPtrs { const float* w[6]; };

__global__ void convw_all_kernel(WPtrs wp) {
    int s = blockIdx.y;
    int din = ((s % 3) == 0) ? 256 : 192;
    int idx = blockIdx.x * 256 + threadIdx.x;
    if (idx >= 192 * din) return;
    int r = idx / din, k = idx - r * din;
    d_w16all[s][r * 256 + k] = __float2half(wp.w[s][((r >> 6) * din + k) * 64 + (r & 63)]);
}

// ---------------- mma.sync GEMM, double-buffered cp.async, 4x2 warp tiling ---
#define KC 64
#define SKA 72
#define A_CH (128 * SKA)
#define B_CH (192 * SKA)
#define BUF_CH (A_CH + B_CH)

__global__ void __launch_bounds__(256) gemm_mma_kernel(
    const __half* __restrict__ H0, const __half* __restrict__ H1,
    int wslot, int din, int n,
    const float* __restrict__ bias0, const float* __restrict__ bias1,
    float* __restrict__ z, __half* __restrict__ h0, __half* __restrict__ h1)
{
    int enc = blockIdx.y;
    const __half* __restrict__ H = enc ? H1 : H0;
    const float* __restrict__ bias = enc ? bias1 : bias0;
    float* zout = z ? z + (size_t)enc * n * 192 : nullptr;
    __half* h16out = enc ? h1 : h0;
    const __half* __restrict__ Wm = d_w16all[enc * 3 + wslot];
    __half* __restrict__ g16 = d_g16[enc];

    extern __shared__ __half smh[];
    int tid = threadIdx.x, wid = tid >> 5, lane = tid & 31;
    int row0 = blockIdx.x * 128;
    int nk = din / KC;

    uint32_t sbase = smem_u32(smh);

    auto load_chunk = [&](int b, int kc) {
        uint32_t abuf = sbase + (uint32_t)(b * BUF_CH) * 2u;
        uint32_t bbuf = abuf + (uint32_t)A_CH * 2u;
        int k0 = kc * KC;
#pragma unroll
        for (int i = 0; i < 4; i++) {
            int idx = tid + 256 * i;
            int r = idx >> 3, c16 = idx & 7;
            const __half* src = H + (size_t)(row0 + r) * din + k0 + c16 * 8;
            uint32_t ok = (row0 + r < n) ? 16u : 0u;
            cp_async16(abuf + (uint32_t)(r * SKA + c16 * 8) * 2u, src, ok);
        }
#pragma unroll
        for (int i = 0; i < 6; i++) {
            int idx = tid + 256 * i;
            int r = idx >> 3, c16 = idx & 7;
            const __half* src = Wm + (size_t)r * 256 + k0 + c16 * 8;
            cp_async16(bbuf + (uint32_t)(r * SKA + c16 * 8) * 2u, src, 16u);
        }
        CP_COMMIT();
    };

    // 4 M-warps x 2 N-warps: each warp owns 32 M rows x 96 N cols
    int mw = wid & 3, nw = wid >> 2;
    int mrow = mw * 32;                     // warp's first M row (2 tiles of 16)
    int cbase = nw * 96;                    // warp's first N col (12 tiles of 8)

    float acc[2][12][4];
#pragma unroll
    for (int m = 0; m < 2; m++)
#pragma unroll
        for (int i = 0; i < 12; i++)
#pragma unroll
            for (int j = 0; j < 4; j++) acc[m][i][j] = 0.f;

    uint32_t a_off0 = (uint32_t)((mrow + (lane & 15)) * SKA + (lane >> 4) * 8) * 2u;
    uint32_t a_off1 = a_off0 + (uint32_t)(16 * SKA) * 2u;
    uint32_t b_off = (uint32_t)(((cbase + (lane >> 4) * 8 + (lane & 7)) * SKA) + ((lane >> 3) & 1) * 8) * 2u;
    uint32_t b_step2 = (uint32_t)(16 * SKA) * 2u;

    load_chunk(0, 0);

    for (int c = 0; c < nk; c++) {
        if (c + 1 < nk) {
            load_chunk((c + 1) & 1, c + 1);
            CP_WAIT(1);
        } else {
            CP_WAIT(0);
        }
        __syncthreads();
        uint32_t abuf = sbase + (uint32_t)((c & 1) * BUF_CH) * 2u;
        uint32_t bbuf = abuf + (uint32_t)A_CH * 2u;
#pragma unroll
        for (int ks = 0; ks < 4; ks++) {
            uint32_t a0, a1, a2, a3, a4, a5, a6, a7;
            asm volatile("ldmatrix.sync.aligned.m8n8.x4.shared.b16 {%0,%1,%2,%3}, [%4];"
                : "=r"(a0), "=r"(a1), "=r"(a2), "=r"(a3) : "r"(abuf + a_off0 + ks * 32));
            asm volatile("ldmatrix.sync.aligned.m8n8.x4.shared.b16 {%0,%1,%2,%3}, [%4];"
                : "=r"(a4), "=r"(a5), "=r"(a6), "=r"(a7) : "r"(abuf + a_off1 + ks * 32));
            uint32_t bb = bbuf + b_off + ks * 32;
#pragma unroll
            for (int nt2 = 0; nt2 < 6; nt2++) {
                uint32_t b0r, b1r, b2r, b3r;
                asm volatile("ldmatrix.sync.aligned.m8n8.x4.shared.b16 {%0,%1,%2,%3}, [%4];"
                    : "=r"(b0r), "=r"(b1r), "=r"(b2r), "=r"(b3r) : "r"(bb));
                asm volatile("mma.sync.aligned.m16n8k16.row.col.f32.f16.f16.f32 "
                    "{%0,%1,%2,%3}, {%4,%5,%6,%7}, {%8,%9}, {%0,%1,%2,%3};"
                    : "+f"(acc[0][2*nt2][0]), "+f"(acc[0][2*nt2][1]), "+f"(acc[0][2*nt2][2]), "+f"(acc[0][2*nt2][3])
                    : "r"(a0), "r"(a1), "r"(a2), "r"(a3), "r"(b0r), "r"(b1r));
                asm volatile("mma.sync.aligned.m16n8k16.row.col.f32.f16.f16.f32 "
                    "{%0,%1,%2,%3}, {%4,%5,%6,%7}, {%8,%9}, {%0,%1,%2,%3};"
                    : "+f"(acc[0][2*nt2+1][0]), "+f"(acc[0][2*nt2+1][1]), "+f"(acc[0][2*nt2+1][2]), "+f"(acc[0][2*nt2+1][3])
                    : "r"(a0), "r"(a1), "r"(a2), "r"(a3), "r"(b2r), "r"(b3r));
                asm volatile("mma.sync.aligned.m16n8k16.row.col.f32.f16.f16.f32 "
                    "{%0,%1,%2,%3}, {%4,%5,%6,%7}, {%8,%9}, {%0,%1,%2,%3};"
                    : "+f"(acc[1][2*nt2][0]), "+f"(acc[1][2*nt2][1]), "+f"(acc[1][2*nt2][2]), "+f"(acc[1][2*nt2][3])
                    : "r"(a4), "r"(a5), "r"(a6), "r"(a7), "r"(b0r), "r"(b1r));
                asm volatile("mma.sync.aligned.m16n8k16.row.col.f32.f16.f16.f32 "
                    "{%0,%1,%2,%3}, {%4,%5,%6,%7}, {%8,%9}, {%0,%1,%2,%3};"
                    : "+f"(acc[1][2*nt2+1][0]), "+f"(acc[1][2*nt2+1][1]), "+f"(acc[1][2*nt2+1][2]), "+f"(acc[1][2*nt2+1][3])
                    : "r"(a4), "r"(a5), "r"(a6), "r"(a7), "r"(b2r), "r"(b3r));
                bb += b_step2;
            }
        }
        __syncthreads();
    }

#pragma unroll
    for (int mt = 0; mt < 2; mt++) {
        int r0 = row0 + mrow + mt * 16 + (lane >> 2);
        int r1 = r0 + 8;
#pragma unroll
        for (int nt = 0; nt < 12; nt++) {
            int c = cbase + nt * 8 + (lane & 3) * 2;
            if (c < 64) {
                float vb0 = bias[c], vb1 = bias[c + 1];
                float o00 = tanh_fast(acc[mt][nt][0] + vb0), o01 = tanh_fast(acc[mt][nt][1] + vb1);
                float o10 = tanh_fast(acc[mt][nt][2] + vb0), o11 = tanh_fast(acc[mt][nt][3] + vb1);
                if (zout) {
                    if (r0 < n) *reinterpret_cast<float2*>(zout + (size_t)r0 * 192 + c) = make_float2(o00, o01);
                    if (r1 < n) *reinterpret_cast<float2*>(zout + (size_t)r1 * 192 + c) = make_float2(o10, o11);
                } else {
                    if (r0 < n) *reinterpret_cast<__half2*>(h16out + (size_t)r0 * 192 + c) = __floats2half2_rn(o00, o01);
                    if (r1 < n) *reinterpret_cast<__half2*>(h16out + (size_t)r1 * 192 + c) = __floats2half2_rn(o10, o11);
                }
            } else {
                int cg = c - 64;
                if (r0 < n) *reinterpret_cast<__half2*>(g16 + (size_t)r0 * 128 + cg) = __floats2half2_rn(acc[mt][nt][0], acc[mt][nt][1]);
                if (r1 < n) *reinterpret_cast<__half2*>(g16 + (size_t)r1 * 128 + cg) = __floats2half2_rn(acc[mt][nt][2], acc[mt][nt][3]);
            }
        }
    }
}

// ------ fused prop over 128 cols: warp per row, broadcast edge loads (8-deep)
__global__ void prop_fused_kernel(int n,
                                  float* __restrict__ z, __half* __restrict__ h0, __half* __restrict__ h1,
                                  const float* __restrict__ b1_0, const float* __restrict__ b1_1)
{
    int enc = blockIdx.y;
    int row = blockIdx.x * 8 + (threadIdx.x >> 5);
    int lane = threadIdx.x & 31;
    if (row >= n) return;
    const __half* __restrict__ g16 = d_g16[enc];
    __half* __restrict__ t16 = d_t16[enc];
    float* zout = z ? z + (size_t)enc * n * 192 : nullptr;
    __half* h16out = enc ? h1 : h0;
    const float* __restrict__ b1 = enc ? b1_1 : b1_0;
    const int* __restrict__ rp = d_rp[enc];
    const int2* __restrict__ edg = d_edge[enc];

    float di = d_dinv[enc][row];
    float sw = di * di;
    uint2 su = reinterpret_cast<const uint2*>(g16 + (size_t)row * 128)[lane];
    float2 s0 = __half22float2(*reinterpret_cast<__half2*>(&su.x));
    float2 s1 = __half22float2(*reinterpret_cast<__half2*>(&su.y));
    float4 acc = make_float4(sw * s0.x, sw * s0.y, sw * s1.x, sw * s1.y);
    int beg = rp[row], end = rp[row + 1];

    float2 a0, a1;
#define ACC128(vv, wv_) \
    a0 = __half22float2(*reinterpret_cast<__half2*>(&vv.x)); \
    a1 = __half22float2(*reinterpret_cast<__half2*>(&vv.y)); \
    acc.x = fmaf(wv_, a0.x, acc.x); acc.y = fmaf(wv_, a0.y, acc.y); \
    acc.z = fmaf(wv_, a1.x, acc.z); acc.w = fmaf(wv_, a1.y, acc.w);

    int u = beg;
    for (; u + 8 <= end; u += 8) {
        int2 E0 = edg[u + 0]; int2 E1 = edg[u + 1];
        int2 E2 = edg[u + 2]; int2 E3 = edg[u + 3];
        int2 E4 = edg[u + 4]; int2 E5 = edg[u + 5];
        int2 E6 = edg[u + 6]; int2 E7 = edg[u + 7];
        uint2 v0 = reinterpret_cast<const uint2*>(g16 + (size_t)E0.x * 128)[lane];
        uint2 v1 = reinterpret_cast<const uint2*>(g16 + (size_t)E1.x * 128)[lane];
        uint2 v2 = reinterpret_cast<const uint2*>(g16 + (size_t)E2.x * 128)[lane];
        uint2 v3 = reinterpret_cast<const uint2*>(g16 + (size_t)E3.x * 128)[lane];
        uint2 v4 = reinterpret_cast<const uint2*>(g16 + (size_t)E4.x * 128)[lane];
        uint2 v5 = reinterpret_cast<const uint2*>(g16 + (size_t)E5.x * 128)[lane];
        uint2 v6 = reinterpret_cast<const uint2*>(g16 + (size_t)E6.x * 128)[lane];
        uint2 v7 = reinterpret_cast<const uint2*>(g16 + (size_t)E7.x * 128)[lane];
        ACC128(v0, __int_as_float(E0.y)) ACC128(v1, __int_as_float(E1.y))
        ACC128(v2, __int_as_float(E2.y)) ACC128(v3, __int_as_float(E3.y))
        ACC128(v4, __int_as_float(E4.y)) ACC128(v5, __int_as_float(E5.y))
        ACC128(v6, __int_as_float(E6.y)) ACC128(v7, __int_as_float(E7.y))
    }
    for (; u < end; u++) {
        int2 E = edg[u];
        uint2 vu = reinterpret_cast<const uint2*>(g16 + (size_t)E.x * 128)[lane];
        ACC128(vu, __int_as_float(E.y))
    }
#undef ACC128

    if (lane < 16) {
        int c = lane * 4;
        float4 o;
        o.x = tanh_fast(acc.x + b1[c + 0]); o.y = tanh_fast(acc.y + b1[c + 1]);
        o.z = tanh_fast(acc.z + b1[c + 2]); o.w = tanh_fast(acc.w + b1[c + 3]);
        if (zout) {
            reinterpret_cast<float4*>(zout + (size_t)row * 192 + 64)[lane] = o;
        } else {
            uint2 hu;
            __half2 q0 = __floats2half2_rn(o.x, o.y);
            __half2 q1 = __floats2half2_rn(o.z, o.w);
            hu.x = *reinterpret_cast<uint32_t*>(&q0);
            hu.y = *reinterpret_cast<uint32_t*>(&q1);
            reinterpret_cast<uint2*>(h16out + (size_t)row * 192 + 64)[lane] = hu;
        }
    } else {
        uint2 tu;
        __half2 q0 = __floats2half2_rn(acc.x, acc.y);
        __half2 q1 = __floats2half2_rn(acc.z, acc.w);
        tu.x = *reinterpret_cast<uint32_t*>(&q0);
        tu.y = *reinterpret_cast<uint32_t*>(&q1);
        reinterpret_cast<uint2*>(t16 + (size_t)row * 64)[lane - 16] = tu;
    }
}

// ------ second hop: warp per row, broadcast edge loads (8-deep) --------------
__global__ void prop64_kernel(int n,
                              float* __restrict__ z, __half* __restrict__ h0, __half* __restrict__ h1,
                              const float* __restrict__ b2_0, const float* __restrict__ b2_1)
{
    int enc = blockIdx.y;
    int row = blockIdx.x * 8 + (threadIdx.x >> 5);
    int lane = threadIdx.x & 31;
    if (row >= n) return;
    const __half* __restrict__ t16 = d_t16[enc];
    float* zout = z ? z + (size_t)enc * n * 192 : nullptr;
    __half* h16out = enc ? h1 : h0;
    const float* __restrict__ b2 = enc ? b2_1 : b2_0;
    const int* __restrict__ rp = d_rp[enc];
    const int2* __restrict__ edg = d_edge[enc];

    float di = d_dinv[enc][row];
    float sw = di * di;
    __half2 sh = reinterpret_cast<const __half2*>(t16 + (size_t)row * 64)[lane];
    float2 s = __half22float2(sh);
    float2 acc = make_float2(sw * s.x, sw * s.y);
    int beg = rp[row], end = rp[row + 1];

    float2 a;
#define ACC64(vv, wv_) \
    a = __half22float2(vv); \
    acc.x = fmaf(wv_, a.x, acc.x); acc.y = fmaf(wv_, a.y, acc.y);

    int u = beg;
    for (; u + 8 <= end; u += 8) {
        int2 E0 = edg[u + 0]; int2 E1 = edg[u + 1];
        int2 E2 = edg[u + 2]; int2 E3 = edg[u + 3];
        int2 E4 = edg[u + 4]; int2 E5 = edg[u + 5];
        int2 E6 = edg[u + 6]; int2 E7 = edg[u + 7];
        __half2 v0 = reinterpret_cast<const __half2*>(t16 + (size_t)E0.x * 64)[lane];
        __half2 v1 = reinterpret_cast<const __half2*>(t16 + (size_t)E1.x * 64)[lane];
        __half2 v2 = reinterpret_cast<const __half2*>(t16 + (size_t)E2.x * 64)[lane];
        __half2 v3 = reinterpret_cast<const __half2*>(t16 + (size_t)E3.x * 64)[lane];
        __half2 v4 = reinterpret_cast<const __half2*>(t16 + (size_t)E4.x * 64)[lane];
        __half2 v5 = reinterpret_cast<const __half2*>(t16 + (size_t)E5.x * 64)[lane];
        __half2 v6 = reinterpret_cast<const __half2*>(t16 + (size_t)E6.x * 64)[lane];
        __half2 v7 = reinterpret_cast<const __half2*>(t16 + (size_t)E7.x * 64)[lane];
        ACC64(v0, __int_as_float(E0.y)) ACC64(v1, __int_as_float(E1.y))
        ACC64(v2, __int_as_float(E2.y)) ACC64(v3, __int_as_float(E3.y))
        ACC64(v4, __int_as_float(E4.y)) ACC64(v5, __int_as_float(E5.y))
        ACC64(v6, __int_as_float(E6.y)) ACC64(v7, __int_as_float(E7.y))
    }
    for (; u < end; u++) {
        int2 E = edg[u];
        __half2 vh = reinterpret_cast<const __half2*>(t16 + (size_t)E.x * 64)[lane];
        ACC64(vh, __int_as_float(E.y))
    }
#undef ACC64

    int c = lane * 2;
    float2 o;
    o.x = tanh_fast(acc.x + b2[c + 0]);
    o.y = tanh_fast(acc.y + b2[c + 1]);
    if (zout) {
        reinterpret_cast<float2*>(zout + (size_t)row * 192 + 128)[lane] = o;
    } else {
        reinterpret_cast<__half2*>(h16out + (size_t)row * 192 + 128)[lane] = __floats2half2_rn(o.x, o.y);
    }
}

extern "C" void kernel_launch(void* const* d_in, const int* in_sizes, int n_in,
                              void* d_out, int out_size)
{
    const float* x = (const float*)d_in[0];
    const void* ei = d_in[1];
    int n = in_sizes[0] / 256;
    int e = in_sizes[1] / 2;
    if (n > NN) n = NN;
    if (e > EE) e = EE;

    static cudaStream_t s2 = nullptr;
    static cudaEvent_t evFork = nullptr, evJoin = nullptr, evDet = nullptr;
    if (s2 == nullptr) {
        cudaStreamCreateWithFlags(&s2, cudaStreamNonBlocking);
        cudaEventCreateWithFlags(&evFork, cudaEventDisableTiming);
        cudaEventCreateWithFlags(&evJoin, cudaEventDisableTiming);
        cudaEventCreateWithFlags(&evDet, cudaEventDisableTiming);
    }

    __half* x16 = nullptr; __half* hA0; __half* hA1; __half* hB0; __half* hB1;
    cudaGetSymbolAddress((void**)&x16, d_x16);
    cudaGetSymbolAddress((void**)&hA0, d_hA);
    hA1 = hA0 + (size_t)NN * 192;
    cudaGetSymbolAddress((void**)&hB0, d_hB);
    hB1 = hB0 + (size_t)NN * 192;
    int* cnt_ptr = nullptr;
    cudaGetSymbolAddress((void**)&cnt_ptr, d_cnt);

    const float* b1_0 = (const float*)d_in[3];
    const float* b2_0 = (const float*)d_in[5];
    const float* b3_0 = (const float*)d_in[7];
    const float* b1_1 = (const float*)d_in[9];
    const float* b2_1 = (const float*)d_in[11];
    const float* b3_1 = (const float*)d_in[13];
    float* z = (float*)d_out;

    int smem_gemm = 2 * BUF_CH * 2;
    cudaFuncSetAttribute(gemm_mma_kernel, cudaFuncAttributeMaxDynamicSharedMemorySize, smem_gemm);

    dim3 ggrid((n + 127) / 128, 2);
    dim3 pgrid((n + 7) / 8, 2);

    WPtrs wp;
    for (int i = 0; i < 6; i++) wp.w[i] = (const float*)d_in[2 + (i / 3) * 6 + (i % 3) * 2];

    // ---- fork: side stream does dtype-detect + conversions + layer-1 GEMM
    cudaEventRecord(evFork, 0);
    cudaStreamWaitEvent(s2, evFork, 0);
    detect_kernel<<<1, 256, 0, s2>>>((const int*)ei);
    cudaEventRecord(evDet, s2);
    convx_kernel<<<(n * 64 + 255) / 256, 256, 0, s2>>>(x, n * 64);
    convw_all_kernel<<<dim3((192 * 256 + 255) / 256, 6), 256, 0, s2>>>(wp);
    gemm_mma_kernel<<<ggrid, 256, smem_gemm, s2>>>(x16, x16, 0, 256, n, b1_0, b1_1, nullptr, hA0, hA1);
    cudaEventRecord(evJoin, s2);

    // ---- main stream: memset d_cnt (parallel with detect), then build chain
    cudaMemsetAsync(cnt_ptr, 0, sizeof(int) * 2 * NN, 0);
    cudaStreamWaitEvent(0, evDet, 0);
    hist_kernel<<<(e + 255) / 256, 256>>>(ei, e);
    int nchunks = (n + 511) / 512;
    dim3 sgrid(nchunks, 2);
    scan1_kernel<<<sgrid, 512>>>(n);
    scan2_kernel<<<1, 1024>>>(nchunks, n);
    scan3_kernel<<<sgrid, 512>>>(n);
    place_kernel<<<(e + 255) / 256, 256>>>(e);

    // ---- join
    cudaStreamWaitEvent(0, evJoin, 0);

    prop_fused_kernel<<<pgrid, 256>>>(n, nullptr, hA0, hA1, b1_0 + 64, b1_1 + 64);
    prop64_kernel<<<pgrid, 256>>>(n, nullptr, hA0, hA1, b1_0 + 128, b1_1 + 128);
    // layer 2
    gemm_mma_kernel<<<ggrid, 256, smem_gemm>>>(hA0, hA1, 1, 192, n, b2_0, b2_1, nullptr, hB0, hB1);
    prop_fused_kernel<<<pgrid, 256>>>(n, nullptr, hB0, hB1, b2_0 + 64, b2_1 + 64);
    prop64_kernel<<<pgrid, 256>>>(n, nullptr, hB0, hB1, b2_0 + 128, b2_1 + 128);
    // layer 3 -> z (fp32 output)
    gemm_mma_kernel<<<ggrid, 256, smem_gemm>>>(hB0, hB1, 2, 192, n, b3_0, b3_1, z, nullptr, nullptr);
    prop_fused_kernel<<<pgrid, 256>>>(n, z, nullptr, nullptr, b3_0 + 64, b3_1 + 64);
    prop64_kernel<<<pgrid, 256>>>(n, z, nullptr, nullptr, b3_0 + 128, b3_1 + 128);
}